// round 12
// baseline (speedup 1.0000x reference)
#include <cuda_runtime.h>
#include <cuda_fp16.h>
#include <cstdint>

// Problem constants
#define BB 16
#define SS 2048
#define HH 512
#define AA 256
#define BS (BB*SS)               // 32768 tokens
#define A_ELEMS ((size_t)BS*HH)  // offset of d in output

// Scratch (device globals — no allocation allowed)
__device__ float g_e[BS];
__device__ float g_w[BS];
__device__ float g_ip[BS];
#define NC 128
#define CS 16
__device__ float g_agg[BB*NC*HH];   // per-chunk aggregate   (flag >= 1)
__device__ float g_inc[BB*NC*HH];   // inclusive prefix      (flag == 2)
__device__ int   g_flag[BB*NC];
// W as fp16 pairs (uint32 = half2), [256 rows][256 pairs]
__device__ unsigned int g_wh[AA*HH/2];

// ---------------------------------------------------------------------------
__device__ __forceinline__ uint32_t smem_u32(const void* p) {
    uint32_t a;
    asm("{ .reg .u64 t; cvta.to.shared.u64 t, %1; cvt.u32.u64 %0, t; }"
        : "=r"(a) : "l"(p));
    return a;
}

#define LDSM_X4(r, addr) \
    asm volatile("ldmatrix.sync.aligned.m8n8.x4.shared.b16 {%0,%1,%2,%3}, [%4];" \
        : "=r"((r)[0]), "=r"((r)[1]), "=r"((r)[2]), "=r"((r)[3]) : "r"(addr))

#define HMMA16816(d, a, b0, b1) \
    asm volatile("mma.sync.aligned.m16n8k16.row.col.f32.f16.f16.f32 " \
        "{%0,%1,%2,%3},{%4,%5,%6,%7},{%8,%9},{%0,%1,%2,%3};" \
        : "+f"((d)[0]), "+f"((d)[1]), "+f"((d)[2]), "+f"((d)[3]) \
        : "r"((a)[0]), "r"((a)[1]), "r"((a)[2]), "r"((a)[3]), "r"(b0), "r"(b1))

#define CP_ASYNC16(dst, src) \
    asm volatile("cp.async.cg.shared.global [%0], [%1], 16;" \
                 :: "r"(dst), "l"(src) : "memory")
#define CP_COMMIT()  asm volatile("cp.async.commit_group;" ::: "memory")
#define CP_WAIT0()   asm volatile("cp.async.wait_group 0;" ::: "memory")

__device__ __forceinline__ float fast_tanh(float v) {
    float t; asm("ex2.approx.f32 %0, %1;" : "=f"(t) : "f"(v * 2.885390081777927f));
    float r; asm("rcp.approx.f32 %0, %1;" : "=f"(r) : "f"(t + 1.0f));
    return fmaf(-2.0f, r, 1.0f);   // tanh(v) = 1 - 2/(e^{2v}+1)
}

// ---------------------------------------------------------------------------
// Kernel 0: W [256,512] fp32 -> fp16 pairs
// ---------------------------------------------------------------------------
__global__ __launch_bounds__(256) void wsplit_kernel(const float* __restrict__ W)
{
    const int i = blockIdx.x * 256 + threadIdx.x;   // pair index
    const float2 v = ((const float2*)W)[i];
    __half2 hp = __floats2half2_rn(v.x, v.y);
    g_wh[i] = *(unsigned int*)&hp;
}

// ---------------------------------------------------------------------------
// Kernel 1: e[t] = sum_a q[a]*tanh( (W x)[t,a] ) via mma.sync fp16.
// CTA tile: M=64 tokens x N=256 (FULL A). 8 warps as 2(m) x 4(n).
// Double-buffered; W via cp.async, X via regs (fp32->fp16 convert).
// ---------------------------------------------------------------------------
#define RSTRIDE 144              // bytes per smem row (64 fp16 + pad)
#define BUFSZ   46080            // X(64*144=9216) + W(256*144=36864)
#define SM_W_OFF 9216
#define SM_Q    92160            // 256 floats
#define SM_TOTAL 93184

__global__ __launch_bounds__(256, 2) void e_mma_kernel(
    const float* __restrict__ x, const float* __restrict__ q)
{
    extern __shared__ __align__(128) char smem[];
    const uint32_t sb = smem_u32(smem);
    const int tid  = threadIdx.x;
    const int lane = tid & 31;
    const int warp = tid >> 5;
    const int warp_m = warp & 1;
    const int warp_n = warp >> 1;
    const size_t m0 = (size_t)blockIdx.x * 64;

    float* sq = (float*)(smem + SM_Q);
    sq[tid] = q[tid];

    float acc[2][8][4];
#pragma unroll
    for (int mt = 0; mt < 2; mt++)
#pragma unroll
        for (int nt = 0; nt < 8; nt++)
#pragma unroll
            for (int j = 0; j < 4; j++) acc[mt][nt][j] = 0.f;

    const uint32_t a_off = (lane & 15) * RSTRIDE + ((lane >> 4) << 4);
    const uint32_t b_off = ((((lane >> 4) & 1) << 3) + (lane & 7)) * RSTRIDE
                         + (((lane >> 3) & 1) << 4);
    const uint32_t ax0 = sb + warp_m * 32 * RSTRIDE + a_off;
    const uint32_t bw0 = sb + SM_W_OFF + warp_n * 64 * RSTRIDE + b_off;

    const uint4* wh4 = (const uint4*)g_wh;   // [a][64 uint4 per row]

    // Prologue: fill buffer 0 for chunk 0
    {
        float4 xv[4];
#pragma unroll
        for (int i = 0; i < 4; i++) {
            const int idx = i * 256 + tid;
            xv[i] = *(const float4*)(x + (m0 + (idx >> 4)) * HH + (idx & 15) * 4);
        }
#pragma unroll
        for (int i = 0; i < 8; i++) {
            const int g  = i * 256 + tid;
            const int row = g >> 3;
            const int cc  = g & 7;
            CP_ASYNC16(sb + SM_W_OFF + row * RSTRIDE + cc * 16,
                       wh4 + (size_t)row * 64 + cc);
        }
        CP_COMMIT();
#pragma unroll
        for (int i = 0; i < 4; i++) {
            const int idx = i * 256 + tid;
            const uint32_t bo = (idx >> 4) * RSTRIDE + (idx & 15) * 8;
            __half2 h01 = __floats2half2_rn(xv[i].x, xv[i].y);
            __half2 h23 = __floats2half2_rn(xv[i].z, xv[i].w);
            unsigned long long hp;
            asm("mov.b64 %0, {%1, %2};" : "=l"(hp)
                : "r"(*(unsigned int*)&h01), "r"(*(unsigned int*)&h23));
            *(unsigned long long*)(smem + bo) = hp;
        }
        CP_WAIT0();
        __syncthreads();
    }

    for (int c = 0; c < 8; c++) {
        const uint32_t cur = (c & 1) * BUFSZ;
        const uint32_t nxt = ((c + 1) & 1) * BUFSZ;

        float4 xv[4];
        if (c < 7) {
            const int kk = (c + 1) * 64;
#pragma unroll
            for (int i = 0; i < 4; i++) {
                const int idx = i * 256 + tid;
                xv[i] = *(const float4*)(x + (m0 + (idx >> 4)) * HH + kk + (idx & 15) * 4);
            }
#pragma unroll
            for (int i = 0; i < 8; i++) {
                const int g  = i * 256 + tid;
                const int row = g >> 3;
                const int cc  = g & 7;
                CP_ASYNC16(sb + nxt + SM_W_OFF + row * RSTRIDE + cc * 16,
                           wh4 + (size_t)row * 64 + (kk >> 3) + cc);
            }
            CP_COMMIT();
        }

        const uint32_t ax = ax0 + cur;
        const uint32_t bw = bw0 + cur;
#pragma unroll
        for (int ks = 0; ks < 4; ks++) {
            uint32_t Bv[16];
#pragma unroll
            for (int jp = 0; jp < 4; jp++)
                LDSM_X4(&Bv[jp * 4], bw + jp * 16 * RSTRIDE + ks * 32);
            uint32_t A0[4], A1[4];
            LDSM_X4(A0, ax + ks * 32);
            LDSM_X4(A1, ax + 16 * RSTRIDE + ks * 32);
#pragma unroll
            for (int nt = 0; nt < 8; nt++) {
                const int bi = (nt >> 1) * 4 + (nt & 1) * 2;
                HMMA16816(acc[0][nt], A0, Bv[bi], Bv[bi + 1]);
            }
#pragma unroll
            for (int nt = 0; nt < 8; nt++) {
                const int bi = (nt >> 1) * 4 + (nt & 1) * 2;
                HMMA16816(acc[1][nt], A1, Bv[bi], Bv[bi + 1]);
            }
        }

        if (c < 7) {
#pragma unroll
            for (int i = 0; i < 4; i++) {
                const int idx = i * 256 + tid;
                const uint32_t bo = (idx >> 4) * RSTRIDE + (idx & 15) * 8;
                __half2 h01 = __floats2half2_rn(xv[i].x, xv[i].y);
                __half2 h23 = __floats2half2_rn(xv[i].z, xv[i].w);
                unsigned long long hp;
                asm("mov.b64 %0, {%1, %2};" : "=l"(hp)
                    : "r"(*(unsigned int*)&h01), "r"(*(unsigned int*)&h23));
                *(unsigned long long*)(smem + nxt + bo) = hp;
            }
            CP_WAIT0();
            __syncthreads();
        }
    }

    // Epilogue: s = sum_cols q[col]*tanh(D) per owned row
    float s[2][2] = {{0.f, 0.f}, {0.f, 0.f}};
#pragma unroll
    for (int mt = 0; mt < 2; mt++)
#pragma unroll
        for (int nt = 0; nt < 8; nt++) {
            const int col = warp_n * 64 + nt * 8 + 2 * (lane & 3);
            const float q0 = sq[col], q1 = sq[col + 1];
            s[mt][0] = fmaf(q0, fast_tanh(acc[mt][nt][0]),
                       fmaf(q1, fast_tanh(acc[mt][nt][1]), s[mt][0]));
            s[mt][1] = fmaf(q0, fast_tanh(acc[mt][nt][2]),
                       fmaf(q1, fast_tanh(acc[mt][nt][3]), s[mt][1]));
        }
#pragma unroll
    for (int mt = 0; mt < 2; mt++)
#pragma unroll
        for (int rh = 0; rh < 2; rh++) {
            float v = s[mt][rh];
            v += __shfl_xor_sync(0xffffffffu, v, 1);
            v += __shfl_xor_sync(0xffffffffu, v, 2);
            s[mt][rh] = v;
        }

    __syncthreads();               // all ldmatrix done; reuse smem
    float* red = (float*)smem;     // [4 warp_n][64 rows]
    if ((lane & 3) == 0) {
#pragma unroll
        for (int mt = 0; mt < 2; mt++)
#pragma unroll
            for (int rh = 0; rh < 2; rh++)
                red[warp_n * 64 + warp_m * 32 + mt * 16 + rh * 8 + (lane >> 2)]
                    = s[mt][rh];
    }
    __syncthreads();
    if (tid < 64)
        g_e[m0 + tid] = (red[tid] + red[64 + tid])
                      + (red[128 + tid] + red[192 + tid]);
}

// ---------------------------------------------------------------------------
// Kernel 2: per-batch  w_t = exp(e_t - max), inclusive prefix P_s, ip = 1/P_s.
// Also resets the decoupled-lookback flags for this replay.
// ---------------------------------------------------------------------------
__global__ __launch_bounds__(256) void scan_kernel()
{
    __shared__ float se[SS];
    __shared__ float sr[256];
    const int b   = blockIdx.x;
    const int tid = threadIdx.x;
    const int base = b * SS;

    if (tid < NC) g_flag[b * NC + tid] = 0;

    for (int i = tid; i < SS; i += 256) se[i] = g_e[base + i];
    __syncthreads();

    float m = -1e30f;
    for (int i = tid; i < SS; i += 256) m = fmaxf(m, se[i]);
    sr[tid] = m;
    __syncthreads();
    for (int o = 128; o; o >>= 1) {
        if (tid < o) sr[tid] = fmaxf(sr[tid], sr[tid + o]);
        __syncthreads();
    }
    const float M = sr[0];
    __syncthreads();

    const int j0 = tid * 8;
    float wloc[8];
    float run = 0.f;
#pragma unroll
    for (int j = 0; j < 8; j++) {
        wloc[j] = expf(se[j0 + j] - M);
        run += wloc[j];
    }
    sr[tid] = run;
    __syncthreads();
    for (int o = 1; o < 256; o <<= 1) {
        const float v = (tid >= o) ? sr[tid - o] : 0.f;
        __syncthreads();
        sr[tid] += v;
        __syncthreads();
    }
    float acc = sr[tid] - run;
#pragma unroll
    for (int j = 0; j < 8; j++) {
        acc += wloc[j];
        g_w [base + j0 + j] = wloc[j];
        g_ip[base + j0 + j] = 1.0f / acc;
    }
}

// ---------------------------------------------------------------------------
// Kernel 3 (fused single-pass): a[b,s,h] via decoupled lookback.
// CTA = one chunk (CS=16 tokens, full H); x tile held in REGISTERS.
// flag: 0 = none, 1 = aggregate ready (g_agg), 2 = inclusive ready (g_inc).
// ---------------------------------------------------------------------------
__global__ __launch_bounds__(128) void ascan_kernel(
    const float* __restrict__ x, float* __restrict__ a_out)
{
    __shared__ float sw[CS];
    __shared__ float sip[CS];
    __shared__ int sflags[16];
    __shared__ int sstop;
    const int bid = blockIdx.x;           // b*NC + c
    const int b   = bid >> 7;
    const int c   = bid & (NC - 1);
    const int tid = threadIdx.x;
    const int tbase = b * SS + c * CS;

    if (tid < CS) {
        sw [tid] = g_w [tbase + tid];
        sip[tid] = g_ip[tbase + tid];
    }
    __syncthreads();

    // Load x tile into registers + compute chunk aggregate
    const float4* xp = (const float4*)(x + (size_t)tbase * HH) + tid;
    float4 xr[CS];
#pragma unroll
    for (int t = 0; t < CS; t++) xr[t] = xp[t * (HH/4)];
    float4 agg = make_float4(0.f, 0.f, 0.f, 0.f);
#pragma unroll
    for (int t = 0; t < CS; t++) {
        const float w = sw[t];
        agg.x = fmaf(w, xr[t].x, agg.x);
        agg.y = fmaf(w, xr[t].y, agg.y);
        agg.z = fmaf(w, xr[t].z, agg.z);
        agg.w = fmaf(w, xr[t].w, agg.w);
    }

    float4 run = make_float4(0.f, 0.f, 0.f, 0.f);
    if (c == 0) {
        // Publish inclusive directly
        ((float4*)(g_inc + (size_t)bid * HH))[tid] = agg;
        __threadfence();
        __syncthreads();
        if (tid == 0) *((volatile int*)&g_flag[bid]) = 2;
    } else {
        // Publish aggregate immediately (before any waiting)
        ((float4*)(g_agg + (size_t)bid * HH))[tid] = agg;
        __threadfence();
        __syncthreads();
        if (tid == 0) *((volatile int*)&g_flag[bid]) = 1;

        // Lookback, window of 16, stop at latest inclusive publisher
        int hi = c;
        bool done = false;
        while (hi > 0 && !done) {
            int lo = hi - 16; if (lo < 0) lo = 0;
            const int cnt = hi - lo;
            if (tid < cnt) {
                int f;
                do { f = *((volatile int*)&g_flag[(b << 7) + lo + tid]); }
                while (f == 0);
                sflags[tid] = f;
            }
            __syncthreads();
            if (tid == 0) {
                int k = -1;
                for (int i = cnt - 1; i >= 0; i--)
                    if (sflags[i] == 2) { k = i; break; }
                sstop = k;
            }
            __syncthreads();
            const int k = sstop;
            __threadfence();   // order value loads after flag observations
            for (int i = (k >= 0 ? k + 1 : 0); i < cnt; i++) {
                const float4 v = __ldcg(
                    (const float4*)(g_agg + (size_t)((b << 7) + lo + i) * HH) + tid);
                run.x += v.x; run.y += v.y; run.z += v.z; run.w += v.w;
            }
            if (k >= 0) {
                const float4 v = __ldcg(
                    (const float4*)(g_inc + (size_t)((b << 7) + lo + k) * HH) + tid);
                run.x += v.x; run.y += v.y; run.z += v.z; run.w += v.w;
                done = true;
            }
            hi = lo;
            __syncthreads();   // sflags reuse
        }

        // Publish inclusive for successors
        const float4 inc = make_float4(run.x + agg.x, run.y + agg.y,
                                       run.z + agg.z, run.w + agg.w);
        ((float4*)(g_inc + (size_t)bid * HH))[tid] = inc;
        __threadfence();
        __syncthreads();
        if (tid == 0) *((volatile int*)&g_flag[bid]) = 2;
    }

    // Emit outputs from register-resident x
    float4 acc = run;
    float4* op = (float4*)(a_out + (size_t)tbase * HH) + tid;
#pragma unroll
    for (int t = 0; t < CS; t++) {
        const float w = sw[t];
        acc.x = fmaf(w, xr[t].x, acc.x);
        acc.y = fmaf(w, xr[t].y, acc.y);
        acc.z = fmaf(w, xr[t].z, acc.z);
        acc.w = fmaf(w, xr[t].w, acc.w);
        const float ip = sip[t];
        __stcs(op + t * (HH/4),
               make_float4(acc.x * ip, acc.y * ip, acc.z * ip, acc.w * ip));
    }
}

// ---------------------------------------------------------------------------
// Kernel 4: d[b,s,t] = (t<=s) ? w[b,t]*ip[b,s] : 0  — 32 rows per CTA,
// 512 threads: one float4 store per thread per row.
// ---------------------------------------------------------------------------
#define DROWS 32
__global__ __launch_bounds__(512) void d_kernel(float* __restrict__ dd)
{
    __shared__ float4 sw4[SS/4];   // 8 KB
    __shared__ float sip[DROWS];
    const int blk = blockIdx.x;            // 1024 blocks
    const int b  = blk >> 6;               // 64 blocks per batch
    const int s0 = (blk & 63) * DROWS;

    const float4* w4 = (const float4*)(g_w + ((size_t)b << 11));
    if (threadIdx.x < SS/4) sw4[threadIdx.x] = w4[threadIdx.x];
    if (threadIdx.x < DROWS) sip[threadIdx.x] = g_ip[(b << 11) + s0 + threadIdx.x];
    __syncthreads();

    const int i  = threadIdx.x;            // float4 index within row
    const int t0 = i * 4;
    const float4 wv = sw4[i];
#pragma unroll 4
    for (int r = 0; r < DROWS; r++) {
        const int s = s0 + r;
        const float ip = sip[r];
        float4 out;
        if (t0 + 3 <= s) {
            out.x = wv.x * ip; out.y = wv.y * ip;
            out.z = wv.z * ip; out.w = wv.w * ip;
        } else if (t0 > s) {
            out.x = out.y = out.z = out.w = 0.f;
        } else {
            out.x = (t0     <= s) ? wv.x * ip : 0.f;
            out.y = (t0 + 1 <= s) ? wv.y * ip : 0.f;
            out.z = (t0 + 2 <= s) ? wv.z * ip : 0.f;
            out.w = (t0 + 3 <= s) ? wv.w * ip : 0.f;
        }
        __stcs((float4*)(dd + ((size_t)(b << 11) + s) * SS) + i, out);
    }
}

// ---------------------------------------------------------------------------
extern "C" void kernel_launch(void* const* d_in, const int* in_sizes, int n_in,
                              void* d_out, int out_size)
{
    const float* x = (const float*)d_in[0];   // [B,S,H]
    const float* W = (const float*)d_in[1];   // [A,H]
    const float* q = (const float*)d_in[2];   // [1,A]
    float* a_out = (float*)d_out;             // [B,S,1,H]
    float* dd    = (float*)d_out + A_ELEMS;   // [B,S,1,S]

    cudaFuncSetAttribute(e_mma_kernel,
                         cudaFuncAttributeMaxDynamicSharedMemorySize, SM_TOTAL);

    wsplit_kernel<<<AA * HH / 512, 256>>>(W);
    e_mma_kernel <<<BS / 64, 256, SM_TOTAL>>>(x, q);
    scan_kernel  <<<BB, 256>>>();
    ascan_kernel <<<BB * NC, 128>>>(x, a_out);
    d_kernel     <<<BS / DROWS, 512>>>(dd);
}

// round 13
// speedup vs baseline: 1.1268x; 1.1268x over previous
#include <cuda_runtime.h>
#include <cuda_fp16.h>
#include <cstdint>

// Problem constants
#define BB 16
#define SS 2048
#define HH 512
#define AA 256
#define BS (BB*SS)               // 32768 tokens
#define A_ELEMS ((size_t)BS*HH)  // offset of d in output

// Scratch (device globals — no allocation allowed)
__device__ float g_e[BS];
__device__ float g_w[BS];
__device__ float g_ip[BS];
#define NC 128
#define CS 16
__device__ float g_chunk[BB*NC*HH];     // 4 MB
__device__ float g_chunkpre[BB*NC*HH];  // 4 MB (exclusive prefix)
// W as fp16 pairs (uint32 = half2), [256 rows][256 pairs]
__device__ unsigned int g_wh[AA*HH/2];

// ---------------------------------------------------------------------------
__device__ __forceinline__ uint32_t smem_u32(const void* p) {
    uint32_t a;
    asm("{ .reg .u64 t; cvta.to.shared.u64 t, %1; cvt.u32.u64 %0, t; }"
        : "=r"(a) : "l"(p));
    return a;
}

#define LDSM_X4(r, addr) \
    asm volatile("ldmatrix.sync.aligned.m8n8.x4.shared.b16 {%0,%1,%2,%3}, [%4];" \
        : "=r"((r)[0]), "=r"((r)[1]), "=r"((r)[2]), "=r"((r)[3]) : "r"(addr))

#define HMMA16816(d, a, b0, b1) \
    asm volatile("mma.sync.aligned.m16n8k16.row.col.f32.f16.f16.f32 " \
        "{%0,%1,%2,%3},{%4,%5,%6,%7},{%8,%9},{%0,%1,%2,%3};" \
        : "+f"((d)[0]), "+f"((d)[1]), "+f"((d)[2]), "+f"((d)[3]) \
        : "r"((a)[0]), "r"((a)[1]), "r"((a)[2]), "r"((a)[3]), "r"(b0), "r"(b1))

#define CP_ASYNC16(dst, src) \
    asm volatile("cp.async.cg.shared.global [%0], [%1], 16;" \
                 :: "r"(dst), "l"(src) : "memory")
#define CP_COMMIT()  asm volatile("cp.async.commit_group;" ::: "memory")
#define CP_WAIT0()   asm volatile("cp.async.wait_group 0;" ::: "memory")

__device__ __forceinline__ float fast_tanh(float v) {
    float t; asm("ex2.approx.f32 %0, %1;" : "=f"(t) : "f"(v * 2.885390081777927f));
    float r; asm("rcp.approx.f32 %0, %1;" : "=f"(r) : "f"(t + 1.0f));
    return fmaf(-2.0f, r, 1.0f);   // tanh(v) = 1 - 2/(e^{2v}+1)
}

// ---------------------------------------------------------------------------
// Kernel 0: W [256,512] fp32 -> fp16 pairs
// ---------------------------------------------------------------------------
__global__ __launch_bounds__(256) void wsplit_kernel(const float* __restrict__ W)
{
    const int i = blockIdx.x * 256 + threadIdx.x;   // pair index
    const float2 v = ((const float2*)W)[i];
    __half2 hp = __floats2half2_rn(v.x, v.y);
    g_wh[i] = *(unsigned int*)&hp;
}

// ---------------------------------------------------------------------------
// Kernel 1: e[t] = sum_a q[a]*tanh( (W x)[t,a] ) via mma.sync fp16.
// CTA tile: M=64 tokens x N=256 (FULL A). 8 warps as 2(m) x 4(n).
// Double-buffered; W via cp.async, X via regs (fp32->fp16 convert).
// ---------------------------------------------------------------------------
#define RSTRIDE 144              // bytes per smem row (64 fp16 + pad)
#define BUFSZ   46080            // X(64*144=9216) + W(256*144=36864)
#define SM_W_OFF 9216
#define SM_Q    92160            // 256 floats
#define SM_TOTAL 93184

__global__ __launch_bounds__(256, 2) void e_mma_kernel(
    const float* __restrict__ x, const float* __restrict__ q)
{
    extern __shared__ __align__(128) char smem[];
    const uint32_t sb = smem_u32(smem);
    const int tid  = threadIdx.x;
    const int lane = tid & 31;
    const int warp = tid >> 5;
    const int warp_m = warp & 1;
    const int warp_n = warp >> 1;
    const size_t m0 = (size_t)blockIdx.x * 64;

    float* sq = (float*)(smem + SM_Q);
    sq[tid] = q[tid];

    float acc[2][8][4];
#pragma unroll
    for (int mt = 0; mt < 2; mt++)
#pragma unroll
        for (int nt = 0; nt < 8; nt++)
#pragma unroll
            for (int j = 0; j < 4; j++) acc[mt][nt][j] = 0.f;

    const uint32_t a_off = (lane & 15) * RSTRIDE + ((lane >> 4) << 4);
    const uint32_t b_off = ((((lane >> 4) & 1) << 3) + (lane & 7)) * RSTRIDE
                         + (((lane >> 3) & 1) << 4);
    const uint32_t ax0 = sb + warp_m * 32 * RSTRIDE + a_off;
    const uint32_t bw0 = sb + SM_W_OFF + warp_n * 64 * RSTRIDE + b_off;

    const uint4* wh4 = (const uint4*)g_wh;   // [a][64 uint4 per row]

    // Prologue: fill buffer 0 for chunk 0
    {
        float4 xv[4];
#pragma unroll
        for (int i = 0; i < 4; i++) {
            const int idx = i * 256 + tid;
            xv[i] = *(const float4*)(x + (m0 + (idx >> 4)) * HH + (idx & 15) * 4);
        }
#pragma unroll
        for (int i = 0; i < 8; i++) {
            const int g  = i * 256 + tid;
            const int row = g >> 3;
            const int cc  = g & 7;
            CP_ASYNC16(sb + SM_W_OFF + row * RSTRIDE + cc * 16,
                       wh4 + (size_t)row * 64 + cc);
        }
        CP_COMMIT();
#pragma unroll
        for (int i = 0; i < 4; i++) {
            const int idx = i * 256 + tid;
            const uint32_t bo = (idx >> 4) * RSTRIDE + (idx & 15) * 8;
            __half2 h01 = __floats2half2_rn(xv[i].x, xv[i].y);
            __half2 h23 = __floats2half2_rn(xv[i].z, xv[i].w);
            unsigned long long hp;
            asm("mov.b64 %0, {%1, %2};" : "=l"(hp)
                : "r"(*(unsigned int*)&h01), "r"(*(unsigned int*)&h23));
            *(unsigned long long*)(smem + bo) = hp;
        }
        CP_WAIT0();
        __syncthreads();
    }

    for (int c = 0; c < 8; c++) {
        const uint32_t cur = (c & 1) * BUFSZ;
        const uint32_t nxt = ((c + 1) & 1) * BUFSZ;

        float4 xv[4];
        if (c < 7) {
            const int kk = (c + 1) * 64;
#pragma unroll
            for (int i = 0; i < 4; i++) {
                const int idx = i * 256 + tid;
                xv[i] = *(const float4*)(x + (m0 + (idx >> 4)) * HH + kk + (idx & 15) * 4);
            }
#pragma unroll
            for (int i = 0; i < 8; i++) {
                const int g  = i * 256 + tid;
                const int row = g >> 3;
                const int cc  = g & 7;
                CP_ASYNC16(sb + nxt + SM_W_OFF + row * RSTRIDE + cc * 16,
                           wh4 + (size_t)row * 64 + (kk >> 3) + cc);
            }
            CP_COMMIT();
        }

        const uint32_t ax = ax0 + cur;
        const uint32_t bw = bw0 + cur;
#pragma unroll
        for (int ks = 0; ks < 4; ks++) {
            uint32_t Bv[16];
#pragma unroll
            for (int jp = 0; jp < 4; jp++)
                LDSM_X4(&Bv[jp * 4], bw + jp * 16 * RSTRIDE + ks * 32);
            uint32_t A0[4], A1[4];
            LDSM_X4(A0, ax + ks * 32);
            LDSM_X4(A1, ax + 16 * RSTRIDE + ks * 32);
#pragma unroll
            for (int nt = 0; nt < 8; nt++) {
                const int bi = (nt >> 1) * 4 + (nt & 1) * 2;
                HMMA16816(acc[0][nt], A0, Bv[bi], Bv[bi + 1]);
            }
#pragma unroll
            for (int nt = 0; nt < 8; nt++) {
                const int bi = (nt >> 1) * 4 + (nt & 1) * 2;
                HMMA16816(acc[1][nt], A1, Bv[bi], Bv[bi + 1]);
            }
        }

        if (c < 7) {
#pragma unroll
            for (int i = 0; i < 4; i++) {
                const int idx = i * 256 + tid;
                const uint32_t bo = (idx >> 4) * RSTRIDE + (idx & 15) * 8;
                __half2 h01 = __floats2half2_rn(xv[i].x, xv[i].y);
                __half2 h23 = __floats2half2_rn(xv[i].z, xv[i].w);
                unsigned long long hp;
                asm("mov.b64 %0, {%1, %2};" : "=l"(hp)
                    : "r"(*(unsigned int*)&h01), "r"(*(unsigned int*)&h23));
                *(unsigned long long*)(smem + nxt + bo) = hp;
            }
            CP_WAIT0();
            __syncthreads();
        }
    }

    // Epilogue: s = sum_cols q[col]*tanh(D) per owned row
    float s[2][2] = {{0.f, 0.f}, {0.f, 0.f}};
#pragma unroll
    for (int mt = 0; mt < 2; mt++)
#pragma unroll
        for (int nt = 0; nt < 8; nt++) {
            const int col = warp_n * 64 + nt * 8 + 2 * (lane & 3);
            const float q0 = sq[col], q1 = sq[col + 1];
            s[mt][0] = fmaf(q0, fast_tanh(acc[mt][nt][0]),
                       fmaf(q1, fast_tanh(acc[mt][nt][1]), s[mt][0]));
            s[mt][1] = fmaf(q0, fast_tanh(acc[mt][nt][2]),
                       fmaf(q1, fast_tanh(acc[mt][nt][3]), s[mt][1]));
        }
#pragma unroll
    for (int mt = 0; mt < 2; mt++)
#pragma unroll
        for (int rh = 0; rh < 2; rh++) {
            float v = s[mt][rh];
            v += __shfl_xor_sync(0xffffffffu, v, 1);
            v += __shfl_xor_sync(0xffffffffu, v, 2);
            s[mt][rh] = v;
        }

    __syncthreads();               // all ldmatrix done; reuse smem
    float* red = (float*)smem;     // [4 warp_n][64 rows]
    if ((lane & 3) == 0) {
#pragma unroll
        for (int mt = 0; mt < 2; mt++)
#pragma unroll
            for (int rh = 0; rh < 2; rh++)
                red[warp_n * 64 + warp_m * 32 + mt * 16 + rh * 8 + (lane >> 2)]
                    = s[mt][rh];
    }
    __syncthreads();
    if (tid < 64)
        g_e[m0 + tid] = (red[tid] + red[64 + tid])
                      + (red[128 + tid] + red[192 + tid]);
}

// ---------------------------------------------------------------------------
// Kernel 2: per-batch  w_t = exp(e_t - max), inclusive prefix P_s, ip = 1/P_s.
// Warp-shuffle scan (3 syncs instead of 16+).
// ---------------------------------------------------------------------------
__global__ __launch_bounds__(256) void scan_kernel()
{
    __shared__ float se[SS];
    __shared__ float swarp[8];
    __shared__ float sM;
    const int b    = blockIdx.x;
    const int tid  = threadIdx.x;
    const int lane = tid & 31;
    const int wid  = tid >> 5;
    const int base = b * SS;

    for (int i = tid; i < SS; i += 256) se[i] = g_e[base + i];
    __syncthreads();

    // max reduce (warp shuffle)
    float m = -1e30f;
    for (int i = tid; i < SS; i += 256) m = fmaxf(m, se[i]);
#pragma unroll
    for (int o = 16; o; o >>= 1)
        m = fmaxf(m, __shfl_xor_sync(0xffffffffu, m, o));
    if (lane == 0) swarp[wid] = m;
    __syncthreads();
    if (tid == 0) {
        float mm = swarp[0];
#pragma unroll
        for (int i = 1; i < 8; i++) mm = fmaxf(mm, swarp[i]);
        sM = mm;
    }
    __syncthreads();
    const float M = sM;

    // per-thread run of 8
    const int j0 = tid * 8;
    float wloc[8];
    float run = 0.f;
#pragma unroll
    for (int j = 0; j < 8; j++) {
        wloc[j] = expf(se[j0 + j] - M);
        run += wloc[j];
    }
    // warp inclusive scan of runs
    float sc = run;
#pragma unroll
    for (int o = 1; o < 32; o <<= 1) {
        const float v = __shfl_up_sync(0xffffffffu, sc, o);
        if (lane >= o) sc += v;
    }
    if (lane == 31) swarp[wid] = sc;
    __syncthreads();
    float woff = 0.f;
    if (wid > 0) {
#pragma unroll
        for (int i = 0; i < 7; i++) if (i < wid) woff += swarp[i];
    }
    float acc = woff + sc - run;   // exclusive offset for this thread
#pragma unroll
    for (int j = 0; j < 8; j++) {
        acc += wloc[j];
        g_w [base + j0 + j] = wloc[j];
        g_ip[base + j0 + j] = 1.0f / acc;
    }
}

// ---------------------------------------------------------------------------
// Kernel 3a: chunk sums T[b,c,h] = sum_{t in chunk} w_t * x[b,t,h]
// ---------------------------------------------------------------------------
__global__ __launch_bounds__(128) void chunk_kernel(const float* __restrict__ x)
{
    __shared__ float sw[CS];
    const int c = blockIdx.x;
    const int b = blockIdx.y;
    const int tbase = b * SS + c * CS;
    if (threadIdx.x < CS) sw[threadIdx.x] = g_w[tbase + threadIdx.x];
    __syncthreads();

    const float4* xp = (const float4*)(x + (size_t)tbase * HH) + threadIdx.x;
    float4 s = make_float4(0.f, 0.f, 0.f, 0.f);
#pragma unroll
    for (int t = 0; t < CS; t++) {
        const float4 v = xp[t * (HH/4)];
        const float w = sw[t];
        s.x = fmaf(w, v.x, s.x);
        s.y = fmaf(w, v.y, s.y);
        s.z = fmaf(w, v.z, s.z);
        s.w = fmaf(w, v.w, s.w);
    }
    __stcg(((float4*)(g_chunk + (size_t)(b * NC + c) * HH)) + threadIdx.x, s);
}

// ---------------------------------------------------------------------------
// Kernel 3p: exclusive prefix over chunks (g_chunk single-use -> ldcs)
// ---------------------------------------------------------------------------
__global__ __launch_bounds__(128) void chunkpre_kernel()
{
    const int b = blockIdx.x;
    const int h = blockIdx.y * 128 + threadIdx.x;
    float acc = 0.f;
#pragma unroll 4
    for (int c = 0; c < NC; c++) {
        const size_t idx = (size_t)(b * NC + c) * HH + h;
        const float v = __ldcs(&g_chunk[idx]);
        __stcg(&g_chunkpre[idx], acc);
        acc += v;
    }
}

// ---------------------------------------------------------------------------
// Kernel 3b: a[b,s,h] = (chunkpre + running sum) * ip[b,s]
// ---------------------------------------------------------------------------
__global__ __launch_bounds__(128) void a_kernel(
    const float* __restrict__ x, float* __restrict__ a_out)
{
    __shared__ float sw[CS];
    __shared__ float sip[CS];
    const int c = blockIdx.x;
    const int b = blockIdx.y;
    const int tbase = b * SS + c * CS;
    if (threadIdx.x < CS) {
        sw [threadIdx.x] = g_w [tbase + threadIdx.x];
        sip[threadIdx.x] = g_ip[tbase + threadIdx.x];
    }
    __syncthreads();

    float4 acc = __ldcs(((const float4*)(g_chunkpre + (size_t)(b * NC + c) * HH))
                        + threadIdx.x);

    const float4* xp = (const float4*)(x + (size_t)tbase * HH) + threadIdx.x;
    float4* op = (float4*)(a_out + (size_t)tbase * HH) + threadIdx.x;
#pragma unroll
    for (int t = 0; t < CS; t++) {
        const float4 v = xp[t * (HH/4)];
        const float w = sw[t];
        acc.x = fmaf(w, v.x, acc.x);
        acc.y = fmaf(w, v.y, acc.y);
        acc.z = fmaf(w, v.z, acc.z);
        acc.w = fmaf(w, v.w, acc.w);
        const float ip = sip[t];
        __stcs(op + t * (HH/4),
               make_float4(acc.x * ip, acc.y * ip, acc.z * ip, acc.w * ip));
    }
}

// ---------------------------------------------------------------------------
// Kernel 4: d[b,s,t] = (t<=s) ? w[b,t]*ip[b,s] : 0  — 32 rows per CTA,
// 512 threads: one float4 store per thread per row.
// ---------------------------------------------------------------------------
#define DROWS 32
__global__ __launch_bounds__(512) void d_kernel(float* __restrict__ dd)
{
    __shared__ float4 sw4[SS/4];   // 8 KB
    __shared__ float sip[DROWS];
    const int blk = blockIdx.x;            // 1024 blocks
    const int b  = blk >> 6;               // 64 blocks per batch
    const int s0 = (blk & 63) * DROWS;

    const float4* w4 = (const float4*)(g_w + ((size_t)b << 11));
    if (threadIdx.x < SS/4) sw4[threadIdx.x] = w4[threadIdx.x];
    if (threadIdx.x < DROWS) sip[threadIdx.x] = g_ip[(b << 11) + s0 + threadIdx.x];
    __syncthreads();

    const int i  = threadIdx.x;            // float4 index within row
    const int t0 = i * 4;
    const float4 wv = sw4[i];
#pragma unroll 4
    for (int r = 0; r < DROWS; r++) {
        const int s = s0 + r;
        const float ip = sip[r];
        float4 out;
        if (t0 + 3 <= s) {
            out.x = wv.x * ip; out.y = wv.y * ip;
            out.z = wv.z * ip; out.w = wv.w * ip;
        } else if (t0 > s) {
            out.x = out.y = out.z = out.w = 0.f;
        } else {
            out.x = (t0     <= s) ? wv.x * ip : 0.f;
            out.y = (t0 + 1 <= s) ? wv.y * ip : 0.f;
            out.z = (t0 + 2 <= s) ? wv.z * ip : 0.f;
            out.w = (t0 + 3 <= s) ? wv.w * ip : 0.f;
        }
        __stcs((float4*)(dd + ((size_t)(b << 11) + s) * SS) + i, out);
    }
}

// ---------------------------------------------------------------------------
extern "C" void kernel_launch(void* const* d_in, const int* in_sizes, int n_in,
                              void* d_out, int out_size)
{
    const float* x = (const float*)d_in[0];   // [B,S,H]
    const float* W = (const float*)d_in[1];   // [A,H]
    const float* q = (const float*)d_in[2];   // [1,A]
    float* a_out = (float*)d_out;             // [B,S,1,H]
    float* dd    = (float*)d_out + A_ELEMS;   // [B,S,1,S]

    cudaFuncSetAttribute(e_mma_kernel,
                         cudaFuncAttributeMaxDynamicSharedMemorySize, SM_TOTAL);

    wsplit_kernel  <<<AA * HH / 512, 256>>>(W);
    e_mma_kernel   <<<BS / 64, 256, SM_TOTAL>>>(x, q);
    scan_kernel    <<<BB, 256>>>();
    chunk_kernel   <<<dim3(NC, BB), 128>>>(x);
    chunkpre_kernel<<<dim3(BB, HH / 128), 128>>>();
    a_kernel       <<<dim3(NC, BB), 128>>>(x, a_out);
    d_kernel       <<<BS / DROWS, 512>>>(dd);
}

// round 15
// speedup vs baseline: 1.1270x; 1.0002x over previous
#include <cuda_runtime.h>
#include <cuda_fp16.h>
#include <cstdint>

// Problem constants
#define BB 16
#define SS 2048
#define HH 512
#define AA 256
#define BS (BB*SS)               // 32768 tokens
#define A_ELEMS ((size_t)BS*HH)  // offset of d in output

// Scratch (device globals — no allocation allowed)
__device__ float g_e[BS];
__device__ float g_w[BS];
__device__ float g_ip[BS];
#define NC 128
#define CS 16
__device__ float g_chunk[BB*NC*HH];     // 4 MB
__device__ float g_chunkpre[BB*NC*HH];  // 4 MB (exclusive prefix)
// W as fp16 pairs (uint32 = half2), [256 rows][256 pairs]
__device__ unsigned int g_wh[AA*HH/2];

// ---------------------------------------------------------------------------
__device__ __forceinline__ uint32_t smem_u32(const void* p) {
    uint32_t a;
    asm("{ .reg .u64 t; cvta.to.shared.u64 t, %1; cvt.u32.u64 %0, t; }"
        : "=r"(a) : "l"(p));
    return a;
}

// 32-byte global load with L2 evict_last (policy set at fill; later kernels hit)
__device__ __forceinline__ void ldg_el8(const float* p, uint32_t* r) {
    asm("ld.global.L2::evict_last.v8.b32 {%0,%1,%2,%3,%4,%5,%6,%7}, [%8];"
        : "=r"(r[0]), "=r"(r[1]), "=r"(r[2]), "=r"(r[3]),
          "=r"(r[4]), "=r"(r[5]), "=r"(r[6]), "=r"(r[7]) : "l"(p));
}

#define LDSM_X4(r, addr) \
    asm volatile("ldmatrix.sync.aligned.m8n8.x4.shared.b16 {%0,%1,%2,%3}, [%4];" \
        : "=r"((r)[0]), "=r"((r)[1]), "=r"((r)[2]), "=r"((r)[3]) : "r"(addr))

#define HMMA16816(d, a, b0, b1) \
    asm volatile("mma.sync.aligned.m16n8k16.row.col.f32.f16.f16.f32 " \
        "{%0,%1,%2,%3},{%4,%5,%6,%7},{%8,%9},{%0,%1,%2,%3};" \
        : "+f"((d)[0]), "+f"((d)[1]), "+f"((d)[2]), "+f"((d)[3]) \
        : "r"((a)[0]), "r"((a)[1]), "r"((a)[2]), "r"((a)[3]), "r"(b0), "r"(b1))

#define CP_ASYNC16(dst, src) \
    asm volatile("cp.async.cg.shared.global [%0], [%1], 16;" \
                 :: "r"(dst), "l"(src) : "memory")
#define CP_COMMIT()  asm volatile("cp.async.commit_group;" ::: "memory")
#define CP_WAIT0()   asm volatile("cp.async.wait_group 0;" ::: "memory")

__device__ __forceinline__ float fast_tanh(float v) {
    float t; asm("ex2.approx.f32 %0, %1;" : "=f"(t) : "f"(v * 2.885390081777927f));
    float r; asm("rcp.approx.f32 %0, %1;" : "=f"(r) : "f"(t + 1.0f));
    return fmaf(-2.0f, r, 1.0f);   // tanh(v) = 1 - 2/(e^{2v}+1)
}

// Convert 8 packed fp32 (as u32) to 4 half2 packed in a uint4
__device__ __forceinline__ uint4 cvt8_fp16(const uint32_t* r) {
    __half2 h01 = __floats2half2_rn(__uint_as_float(r[0]), __uint_as_float(r[1]));
    __half2 h23 = __floats2half2_rn(__uint_as_float(r[2]), __uint_as_float(r[3]));
    __half2 h45 = __floats2half2_rn(__uint_as_float(r[4]), __uint_as_float(r[5]));
    __half2 h67 = __floats2half2_rn(__uint_as_float(r[6]), __uint_as_float(r[7]));
    uint4 o;
    o.x = *(unsigned int*)&h01;
    o.y = *(unsigned int*)&h23;
    o.z = *(unsigned int*)&h45;
    o.w = *(unsigned int*)&h67;
    return o;
}

// ---------------------------------------------------------------------------
// Kernel 0: W [256,512] fp32 -> fp16 pairs
// ---------------------------------------------------------------------------
__global__ __launch_bounds__(256) void wsplit_kernel(const float* __restrict__ W)
{
    const int i = blockIdx.x * 256 + threadIdx.x;   // pair index
    const float2 v = ((const float2*)W)[i];
    __half2 hp = __floats2half2_rn(v.x, v.y);
    g_wh[i] = *(unsigned int*)&hp;
}

// ---------------------------------------------------------------------------
// Kernel 1: e[t] = sum_a q[a]*tanh( (W x)[t,a] ) via mma.sync fp16.
// CTA tile: M=64 tokens x N=256 (FULL A). 8 warps as 2(m) x 4(n).
// Double-buffered; W via cp.async, X via v8 evict_last loads (L2-resident
// for the chunk/a kernels that re-read x afterwards).
// ---------------------------------------------------------------------------
#define RSTRIDE 144              // bytes per smem row (64 fp16 + pad)
#define BUFSZ   46080            // X(64*144=9216) + W(256*144=36864)
#define SM_W_OFF 9216
#define SM_Q    92160            // 256 floats
#define SM_TOTAL 93184

__global__ __launch_bounds__(256, 2) void e_mma_kernel(
    const float* __restrict__ x, const float* __restrict__ q)
{
    extern __shared__ __align__(128) char smem[];
    const uint32_t sb = smem_u32(smem);
    const int tid  = threadIdx.x;
    const int lane = tid & 31;
    const int warp = tid >> 5;
    const int warp_m = warp & 1;
    const int warp_n = warp >> 1;
    const size_t m0 = (size_t)blockIdx.x * 64;

    float* sq = (float*)(smem + SM_Q);
    sq[tid] = q[tid];

    float acc[2][8][4];
#pragma unroll
    for (int mt = 0; mt < 2; mt++)
#pragma unroll
        for (int nt = 0; nt < 8; nt++)
#pragma unroll
            for (int j = 0; j < 4; j++) acc[mt][nt][j] = 0.f;

    const uint32_t a_off = (lane & 15) * RSTRIDE + ((lane >> 4) << 4);
    const uint32_t b_off = ((((lane >> 4) & 1) << 3) + (lane & 7)) * RSTRIDE
                         + (((lane >> 3) & 1) << 4);
    const uint32_t ax0 = sb + warp_m * 32 * RSTRIDE + a_off;
    const uint32_t bw0 = sb + SM_W_OFF + warp_n * 64 * RSTRIDE + b_off;

    const uint4* wh4 = (const uint4*)g_wh;   // [a][64 uint4 per row]

    // X tile indexing: 64 rows x 64 cols fp32 = 512 x 32B; 256 thr x 2 v8 loads
    const int xrow0 = tid >> 3;          // idx = 0*256+tid
    const int xc8_0 = tid & 7;
    const int xrow1 = (256 + tid) >> 3;  // idx = 1*256+tid
    const int xc8_1 = tid & 7;           // (256+tid)&7 == tid&7

    // Prologue: fill buffer 0 for chunk 0
    {
        uint32_t xr[2][8];
        ldg_el8(x + (m0 + xrow0) * HH + xc8_0 * 8, xr[0]);
        ldg_el8(x + (m0 + xrow1) * HH + xc8_1 * 8, xr[1]);
#pragma unroll
        for (int i = 0; i < 8; i++) {
            const int g  = i * 256 + tid;
            const int row = g >> 3;
            const int cc  = g & 7;
            CP_ASYNC16(sb + SM_W_OFF + row * RSTRIDE + cc * 16,
                       wh4 + (size_t)row * 64 + cc);
        }
        CP_COMMIT();
        *(uint4*)(smem + xrow0 * RSTRIDE + xc8_0 * 16) = cvt8_fp16(xr[0]);
        *(uint4*)(smem + xrow1 * RSTRIDE + xc8_1 * 16) = cvt8_fp16(xr[1]);
        CP_WAIT0();
        __syncthreads();
    }

    for (int c = 0; c < 8; c++) {
        const uint32_t cur = (c & 1) * BUFSZ;
        const uint32_t nxt = ((c + 1) & 1) * BUFSZ;

        uint32_t xr[2][8];
        if (c < 7) {
            const int kk = (c + 1) * 64;
            ldg_el8(x + (m0 + xrow0) * HH + kk + xc8_0 * 8, xr[0]);
            ldg_el8(x + (m0 + xrow1) * HH + kk + xc8_1 * 8, xr[1]);
#pragma unroll
            for (int i = 0; i < 8; i++) {
                const int g  = i * 256 + tid;
                const int row = g >> 3;
                const int cc  = g & 7;
                CP_ASYNC16(sb + nxt + SM_W_OFF + row * RSTRIDE + cc * 16,
                           wh4 + (size_t)row * 64 + (kk >> 3) + cc);
            }
            CP_COMMIT();
        }

        const uint32_t ax = ax0 + cur;
        const uint32_t bw = bw0 + cur;
#pragma unroll
        for (int ks = 0; ks < 4; ks++) {
            uint32_t Bv[16];
#pragma unroll
            for (int jp = 0; jp < 4; jp++)
                LDSM_X4(&Bv[jp * 4], bw + jp * 16 * RSTRIDE + ks * 32);
            uint32_t A0[4], A1[4];
            LDSM_X4(A0, ax + ks * 32);
            LDSM_X4(A1, ax + 16 * RSTRIDE + ks * 32);
#pragma unroll
            for (int nt = 0; nt < 8; nt++) {
                const int bi = (nt >> 1) * 4 + (nt & 1) * 2;
                HMMA16816(acc[0][nt], A0, Bv[bi], Bv[bi + 1]);
            }
#pragma unroll
            for (int nt = 0; nt < 8; nt++) {
                const int bi = (nt >> 1) * 4 + (nt & 1) * 2;
                HMMA16816(acc[1][nt], A1, Bv[bi], Bv[bi + 1]);
            }
        }

        if (c < 7) {
            *(uint4*)(smem + nxt + xrow0 * RSTRIDE + xc8_0 * 16) = cvt8_fp16(xr[0]);
            *(uint4*)(smem + nxt + xrow1 * RSTRIDE + xc8_1 * 16) = cvt8_fp16(xr[1]);
            CP_WAIT0();
            __syncthreads();
        }
    }

    // Epilogue: s = sum_cols q[col]*tanh(D) per owned row
    float s[2][2] = {{0.f, 0.f}, {0.f, 0.f}};
#pragma unroll
    for (int mt = 0; mt < 2; mt++)
#pragma unroll
        for (int nt = 0; nt < 8; nt++) {
            const int col = warp_n * 64 + nt * 8 + 2 * (lane & 3);
            const float q0 = sq[col], q1 = sq[col + 1];
            s[mt][0] = fmaf(q0, fast_tanh(acc[mt][nt][0]),
                       fmaf(q1, fast_tanh(acc[mt][nt][1]), s[mt][0]));
            s[mt][1] = fmaf(q0, fast_tanh(acc[mt][nt][2]),
                       fmaf(q1, fast_tanh(acc[mt][nt][3]), s[mt][1]));
        }
#pragma unroll
    for (int mt = 0; mt < 2; mt++)
#pragma unroll
        for (int rh = 0; rh < 2; rh++) {
            float v = s[mt][rh];
            v += __shfl_xor_sync(0xffffffffu, v, 1);
            v += __shfl_xor_sync(0xffffffffu, v, 2);
            s[mt][rh] = v;
        }

    __syncthreads();               // all ldmatrix done; reuse smem
    float* red = (float*)smem;     // [4 warp_n][64 rows]
    if ((lane & 3) == 0) {
#pragma unroll
        for (int mt = 0; mt < 2; mt++)
#pragma unroll
            for (int rh = 0; rh < 2; rh++)
                red[warp_n * 64 + warp_m * 32 + mt * 16 + rh * 8 + (lane >> 2)]
                    = s[mt][rh];
    }
    __syncthreads();
    if (tid < 64)
        g_e[m0 + tid] = (red[tid] + red[64 + tid])
                      + (red[128 + tid] + red[192 + tid]);
}

// ---------------------------------------------------------------------------
// Kernel 2: per-batch  w_t = exp(e_t - max), inclusive prefix P_s, ip = 1/P_s.
// Warp-shuffle scan.
// ---------------------------------------------------------------------------
__global__ __launch_bounds__(256) void scan_kernel()
{
    __shared__ float se[SS];
    __shared__ float swarp[8];
    __shared__ float sM;
    const int b    = blockIdx.x;
    const int tid  = threadIdx.x;
    const int lane = tid & 31;
    const int wid  = tid >> 5;
    const int base = b * SS;

    for (int i = tid; i < SS; i += 256) se[i] = g_e[base + i];
    __syncthreads();

    float m = -1e30f;
    for (int i = tid; i < SS; i += 256) m = fmaxf(m, se[i]);
#pragma unroll
    for (int o = 16; o; o >>= 1)
        m = fmaxf(m, __shfl_xor_sync(0xffffffffu, m, o));
    if (lane == 0) swarp[wid] = m;
    __syncthreads();
    if (tid == 0) {
        float mm = swarp[0];
#pragma unroll
        for (int i = 1; i < 8; i++) mm = fmaxf(mm, swarp[i]);
        sM = mm;
    }
    __syncthreads();
    const float M = sM;

    const int j0 = tid * 8;
    float wloc[8];
    float run = 0.f;
#pragma unroll
    for (int j = 0; j < 8; j++) {
        wloc[j] = expf(se[j0 + j] - M);
        run += wloc[j];
    }
    float sc = run;
#pragma unroll
    for (int o = 1; o < 32; o <<= 1) {
        const float v = __shfl_up_sync(0xffffffffu, sc, o);
        if (lane >= o) sc += v;
    }
    if (lane == 31) swarp[wid] = sc;
    __syncthreads();
    float woff = 0.f;
    if (wid > 0) {
#pragma unroll
        for (int i = 0; i < 7; i++) if (i < wid) woff += swarp[i];
    }
    float acc = woff + sc - run;
#pragma unroll
    for (int j = 0; j < 8; j++) {
        acc += wloc[j];
        g_w [base + j0 + j] = wloc[j];
        g_ip[base + j0 + j] = 1.0f / acc;
    }
}

// ---------------------------------------------------------------------------
// Kernel 3a: chunk sums — x should hit L2 (evict_last fills from e_mma)
// ---------------------------------------------------------------------------
__global__ __launch_bounds__(128) void chunk_kernel(const float* __restrict__ x)
{
    __shared__ float sw[CS];
    const int c = blockIdx.x;
    const int b = blockIdx.y;
    const int tbase = b * SS + c * CS;
    if (threadIdx.x < CS) sw[threadIdx.x] = g_w[tbase + threadIdx.x];
    __syncthreads();

    const float4* xp = (const float4*)(x + (size_t)tbase * HH) + threadIdx.x;
    float4 s = make_float4(0.f, 0.f, 0.f, 0.f);
#pragma unroll
    for (int t = 0; t < CS; t++) {
        const float4 v = xp[t * (HH/4)];
        const float w = sw[t];
        s.x = fmaf(w, v.x, s.x);
        s.y = fmaf(w, v.y, s.y);
        s.z = fmaf(w, v.z, s.z);
        s.w = fmaf(w, v.w, s.w);
    }
    __stcg(((float4*)(g_chunk + (size_t)(b * NC + c) * HH)) + threadIdx.x, s);
}

// ---------------------------------------------------------------------------
// Kernel 3p: exclusive prefix over chunks
// ---------------------------------------------------------------------------
__global__ __launch_bounds__(128) void chunkpre_kernel()
{
    const int b = blockIdx.x;
    const int h = blockIdx.y * 128 + threadIdx.x;
    float acc = 0.f;
#pragma unroll 4
    for (int c = 0; c < NC; c++) {
        const size_t idx = (size_t)(b * NC + c) * HH + h;
        const float v = __ldcs(&g_chunk[idx]);
        __stcg(&g_chunkpre[idx], acc);
        acc += v;
    }
}

// ---------------------------------------------------------------------------
// Kernel 3b: a[b,s,h] — x read from L2 (last use -> evict-first ldcs)
// ---------------------------------------------------------------------------
__global__ __launch_bounds__(128) void a_kernel(
    const float* __restrict__ x, float* __restrict__ a_out)
{
    __shared__ float sw[CS];
    __shared__ float sip[CS];
    const int c = blockIdx.x;
    const int b = blockIdx.y;
    const int tbase = b * SS + c * CS;
    if (threadIdx.x < CS) {
        sw [threadIdx.x] = g_w [tbase + threadIdx.x];
        sip[threadIdx.x] = g_ip[tbase + threadIdx.x];
    }
    __syncthreads();

    float4 acc = __ldcs(((const float4*)(g_chunkpre + (size_t)(b * NC + c) * HH))
                        + threadIdx.x);

    const float4* xp = (const float4*)(x + (size_t)tbase * HH) + threadIdx.x;
    float4* op = (float4*)(a_out + (size_t)tbase * HH) + threadIdx.x;
#pragma unroll
    for (int t = 0; t < CS; t++) {
        const float4 v = __ldcs(xp + t * (HH/4));   // last reader of x
        const float w = sw[t];
        acc.x = fmaf(w, v.x, acc.x);
        acc.y = fmaf(w, v.y, acc.y);
        acc.z = fmaf(w, v.z, acc.z);
        acc.w = fmaf(w, v.w, acc.w);
        const float ip = sip[t];
        __stcs(op + t * (HH/4),
               make_float4(acc.x * ip, acc.y * ip, acc.z * ip, acc.w * ip));
    }
}

// ---------------------------------------------------------------------------
// Kernel 4: d[b,s,t] = (t<=s) ? w[b,t]*ip[b,s] : 0  — 32 rows per CTA,
// 512 threads: one float4 store per thread per row.
// ---------------------------------------------------------------------------
#define DROWS 32
__global__ __launch_bounds__(512) void d_kernel(float* __restrict__ dd)
{
    __shared__ float4 sw4[SS/4];   // 8 KB
    __shared__ float sip[DROWS];
    const int blk = blockIdx.x;            // 1024 blocks
    const int b  = blk >> 6;               // 64 blocks per batch
    const int s0 = (blk & 63) * DROWS;

    const float4* w4 = (const float4*)(g_w + ((size_t)b << 11));
    if (threadIdx.x < SS/4) sw4[threadIdx.x] = w4[threadIdx.x];
    if (threadIdx.x < DROWS) sip[threadIdx.x] = g_ip[(b << 11) + s0 + threadIdx.x];
    __syncthreads();

    const int i  = threadIdx.x;            // float4 index within row
    const int t0 = i * 4;
    const float4 wv = sw4[i];
#pragma unroll 4
    for (int r = 0; r < DROWS; r++) {
        const int s = s0 + r;
        const float ip = sip[r];
        float4 out;
        if (t0 + 3 <= s) {
            out.x = wv.x * ip; out.y = wv.y * ip;
            out.z = wv.z * ip; out.w = wv.w * ip;
        } else if (t0 > s) {
            out.x = out.y = out.z = out.w = 0.f;
        } else {
            out.x = (t0     <= s) ? wv.x * ip : 0.f;
            out.y = (t0 + 1 <= s) ? wv.y * ip : 0.f;
            out.z = (t0 + 2 <= s) ? wv.z * ip : 0.f;
            out.w = (t0 + 3 <= s) ? wv.w * ip : 0.f;
        }
        __stcs((float4*)(dd + ((size_t)(b << 11) + s) * SS) + i, out);
    }
}

// ---------------------------------------------------------------------------
extern "C" void kernel_launch(void* const* d_in, const int* in_sizes, int n_in,
                              void* d_out, int out_size)
{
    const float* x = (const float*)d_in[0];   // [B,S,H]
    const float* W = (const float*)d_in[1];   // [A,H]
    const float* q = (const float*)d_in[2];   // [1,A]
    float* a_out = (float*)d_out;             // [B,S,1,H]
    float* dd    = (float*)d_out + A_ELEMS;   // [B,S,1,S]

    cudaFuncSetAttribute(e_mma_kernel,
                         cudaFuncAttributeMaxDynamicSharedMemorySize, SM_TOTAL);

    wsplit_kernel  <<<AA * HH / 512, 256>>>(W);
    e_mma_kernel   <<<BS / 64, 256, SM_TOTAL>>>(x, q);
    scan_kernel    <<<BB, 256>>>();
    chunk_kernel   <<<dim3(NC, BB), 128>>>(x);
    chunkpre_kernel<<<dim3(BB, HH / 128), 128>>>();
    a_kernel       <<<dim3(NC, BB), 128>>>(x, a_out);
    d_kernel       <<<BS / DROWS, 512>>>(dd);
}

// round 16
// speedup vs baseline: 1.2067x; 1.0707x over previous
#include <cuda_runtime.h>
#include <cuda_fp16.h>
#include <cstdint>

// Problem constants
#define BB 16
#define SS 2048
#define HH 512
#define AA 256
#define BS (BB*SS)               // 32768 tokens
#define A_ELEMS ((size_t)BS*HH)  // offset of d in output

// Scratch (device globals — no allocation allowed)
__device__ float g_e[BS];
__device__ float g_w[BS];
__device__ float g_ip[BS];
#define NC 128
#define CS 16
__device__ float g_chunk[BB*NC*HH];     // 4 MB
__device__ float g_chunkpre[BB*NC*HH];  // 4 MB (exclusive prefix)
// W as fp16 pairs (uint32 = half2), [256 rows][256 pairs]
__device__ unsigned int g_wh[AA*HH/2];

// ---------------------------------------------------------------------------
#define GDC_WAIT()   asm volatile("griddepcontrol.wait;" ::: "memory")
#define GDC_LAUNCH() asm volatile("griddepcontrol.launch_dependents;" ::: "memory")

__device__ __forceinline__ uint32_t smem_u32(const void* p) {
    uint32_t a;
    asm("{ .reg .u64 t; cvta.to.shared.u64 t, %1; cvt.u32.u64 %0, t; }"
        : "=r"(a) : "l"(p));
    return a;
}

#define LDSM_X4(r, addr) \
    asm volatile("ldmatrix.sync.aligned.m8n8.x4.shared.b16 {%0,%1,%2,%3}, [%4];" \
        : "=r"((r)[0]), "=r"((r)[1]), "=r"((r)[2]), "=r"((r)[3]) : "r"(addr))

#define HMMA16816(d, a, b0, b1) \
    asm volatile("mma.sync.aligned.m16n8k16.row.col.f32.f16.f16.f32 " \
        "{%0,%1,%2,%3},{%4,%5,%6,%7},{%8,%9},{%0,%1,%2,%3};" \
        : "+f"((d)[0]), "+f"((d)[1]), "+f"((d)[2]), "+f"((d)[3]) \
        : "r"((a)[0]), "r"((a)[1]), "r"((a)[2]), "r"((a)[3]), "r"(b0), "r"(b1))

#define CP_ASYNC16(dst, src) \
    asm volatile("cp.async.cg.shared.global [%0], [%1], 16;" \
                 :: "r"(dst), "l"(src) : "memory")
#define CP_COMMIT()  asm volatile("cp.async.commit_group;" ::: "memory")
#define CP_WAIT0()   asm volatile("cp.async.wait_group 0;" ::: "memory")

__device__ __forceinline__ float fast_tanh(float v) {
    float t; asm("ex2.approx.f32 %0, %1;" : "=f"(t) : "f"(v * 2.885390081777927f));
    float r; asm("rcp.approx.f32 %0, %1;" : "=f"(r) : "f"(t + 1.0f));
    return fmaf(-2.0f, r, 1.0f);   // tanh(v) = 1 - 2/(e^{2v}+1)
}

// ---------------------------------------------------------------------------
// Kernel 0: W [256,512] fp32 -> fp16 pairs
// ---------------------------------------------------------------------------
__global__ __launch_bounds__(256) void wsplit_kernel(const float* __restrict__ W)
{
    GDC_LAUNCH();
    const int i = blockIdx.x * 256 + threadIdx.x;   // pair index
    const float2 v = ((const float2*)W)[i];
    __half2 hp = __floats2half2_rn(v.x, v.y);
    g_wh[i] = *(unsigned int*)&hp;
}

// ---------------------------------------------------------------------------
// Kernel 1: e[t] = sum_a q[a]*tanh( (W x)[t,a] ) via mma.sync fp16.
// CTA tile: M=64 tokens x N=256 (FULL A). 8 warps as 2(m) x 4(n).
// Double-buffered; W via cp.async, X via regs (fp32->fp16 convert).
// PDL: x-prologue overlaps wsplit; wait before first g_wh read.
// ---------------------------------------------------------------------------
#define RSTRIDE 144              // bytes per smem row (64 fp16 + pad)
#define BUFSZ   46080            // X(64*144=9216) + W(256*144=36864)
#define SM_W_OFF 9216
#define SM_Q    92160            // 256 floats
#define SM_TOTAL 93184

__global__ __launch_bounds__(256, 2) void e_mma_kernel(
    const float* __restrict__ x, const float* __restrict__ q)
{
    extern __shared__ __align__(128) char smem[];
    const uint32_t sb = smem_u32(smem);
    const int tid  = threadIdx.x;
    const int lane = tid & 31;
    const int warp = tid >> 5;
    const int warp_m = warp & 1;
    const int warp_n = warp >> 1;
    const size_t m0 = (size_t)blockIdx.x * 64;

    float* sq = (float*)(smem + SM_Q);
    sq[tid] = q[tid];

    float acc[2][8][4];
#pragma unroll
    for (int mt = 0; mt < 2; mt++)
#pragma unroll
        for (int nt = 0; nt < 8; nt++)
#pragma unroll
            for (int j = 0; j < 4; j++) acc[mt][nt][j] = 0.f;

    const uint32_t a_off = (lane & 15) * RSTRIDE + ((lane >> 4) << 4);
    const uint32_t b_off = ((((lane >> 4) & 1) << 3) + (lane & 7)) * RSTRIDE
                         + (((lane >> 3) & 1) << 4);
    const uint32_t ax0 = sb + warp_m * 32 * RSTRIDE + a_off;
    const uint32_t bw0 = sb + SM_W_OFF + warp_n * 64 * RSTRIDE + b_off;

    const uint4* wh4 = (const uint4*)g_wh;   // [a][64 uint4 per row]

    // Prologue: fill buffer 0 for chunk 0
    {
        float4 xv[4];
#pragma unroll
        for (int i = 0; i < 4; i++) {
            const int idx = i * 256 + tid;
            xv[i] = *(const float4*)(x + (m0 + (idx >> 4)) * HH + (idx & 15) * 4);
        }
        GDC_WAIT();            // g_wh ready (wsplit done)
        GDC_LAUNCH();          // let scan roll out during our execution
#pragma unroll
        for (int i = 0; i < 8; i++) {
            const int g  = i * 256 + tid;
            const int row = g >> 3;
            const int cc  = g & 7;
            CP_ASYNC16(sb + SM_W_OFF + row * RSTRIDE + cc * 16,
                       wh4 + (size_t)row * 64 + cc);
        }
        CP_COMMIT();
#pragma unroll
        for (int i = 0; i < 4; i++) {
            const int idx = i * 256 + tid;
            const uint32_t bo = (idx >> 4) * RSTRIDE + (idx & 15) * 8;
            __half2 h01 = __floats2half2_rn(xv[i].x, xv[i].y);
            __half2 h23 = __floats2half2_rn(xv[i].z, xv[i].w);
            unsigned long long hp;
            asm("mov.b64 %0, {%1, %2};" : "=l"(hp)
                : "r"(*(unsigned int*)&h01), "r"(*(unsigned int*)&h23));
            *(unsigned long long*)(smem + bo) = hp;
        }
        CP_WAIT0();
        __syncthreads();
    }

    for (int c = 0; c < 8; c++) {
        const uint32_t cur = (c & 1) * BUFSZ;
        const uint32_t nxt = ((c + 1) & 1) * BUFSZ;

        float4 xv[4];
        if (c < 7) {
            const int kk = (c + 1) * 64;
#pragma unroll
            for (int i = 0; i < 4; i++) {
                const int idx = i * 256 + tid;
                xv[i] = *(const float4*)(x + (m0 + (idx >> 4)) * HH + kk + (idx & 15) * 4);
            }
#pragma unroll
            for (int i = 0; i < 8; i++) {
                const int g  = i * 256 + tid;
                const int row = g >> 3;
                const int cc  = g & 7;
                CP_ASYNC16(sb + nxt + SM_W_OFF + row * RSTRIDE + cc * 16,
                           wh4 + (size_t)row * 64 + (kk >> 3) + cc);
            }
            CP_COMMIT();
        }

        const uint32_t ax = ax0 + cur;
        const uint32_t bw = bw0 + cur;
#pragma unroll
        for (int ks = 0; ks < 4; ks++) {
            uint32_t Bv[16];
#pragma unroll
            for (int jp = 0; jp < 4; jp++)
                LDSM_X4(&Bv[jp * 4], bw + jp * 16 * RSTRIDE + ks * 32);
            uint32_t A0[4], A1[4];
            LDSM_X4(A0, ax + ks * 32);
            LDSM_X4(A1, ax + 16 * RSTRIDE + ks * 32);
#pragma unroll
            for (int nt = 0; nt < 8; nt++) {
                const int bi = (nt >> 1) * 4 + (nt & 1) * 2;
                HMMA16816(acc[0][nt], A0, Bv[bi], Bv[bi + 1]);
            }
#pragma unroll
            for (int nt = 0; nt < 8; nt++) {
                const int bi = (nt >> 1) * 4 + (nt & 1) * 2;
                HMMA16816(acc[1][nt], A1, Bv[bi], Bv[bi + 1]);
            }
        }

        if (c < 7) {
#pragma unroll
            for (int i = 0; i < 4; i++) {
                const int idx = i * 256 + tid;
                const uint32_t bo = (idx >> 4) * RSTRIDE + (idx & 15) * 8;
                __half2 h01 = __floats2half2_rn(xv[i].x, xv[i].y);
                __half2 h23 = __floats2half2_rn(xv[i].z, xv[i].w);
                unsigned long long hp;
                asm("mov.b64 %0, {%1, %2};" : "=l"(hp)
                    : "r"(*(unsigned int*)&h01), "r"(*(unsigned int*)&h23));
                *(unsigned long long*)(smem + nxt + bo) = hp;
            }
            CP_WAIT0();
            __syncthreads();
        }
    }

    // Epilogue: s = sum_cols q[col]*tanh(D) per owned row
    float s[2][2] = {{0.f, 0.f}, {0.f, 0.f}};
#pragma unroll
    for (int mt = 0; mt < 2; mt++)
#pragma unroll
        for (int nt = 0; nt < 8; nt++) {
            const int col = warp_n * 64 + nt * 8 + 2 * (lane & 3);
            const float q0 = sq[col], q1 = sq[col + 1];
            s[mt][0] = fmaf(q0, fast_tanh(acc[mt][nt][0]),
                       fmaf(q1, fast_tanh(acc[mt][nt][1]), s[mt][0]));
            s[mt][1] = fmaf(q0, fast_tanh(acc[mt][nt][2]),
                       fmaf(q1, fast_tanh(acc[mt][nt][3]), s[mt][1]));
        }
#pragma unroll
    for (int mt = 0; mt < 2; mt++)
#pragma unroll
        for (int rh = 0; rh < 2; rh++) {
            float v = s[mt][rh];
            v += __shfl_xor_sync(0xffffffffu, v, 1);
            v += __shfl_xor_sync(0xffffffffu, v, 2);
            s[mt][rh] = v;
        }

    __syncthreads();               // all ldmatrix done; reuse smem
    float* red = (float*)smem;     // [4 warp_n][64 rows]
    if ((lane & 3) == 0) {
#pragma unroll
        for (int mt = 0; mt < 2; mt++)
#pragma unroll
            for (int rh = 0; rh < 2; rh++)
                red[warp_n * 64 + warp_m * 32 + mt * 16 + rh * 8 + (lane >> 2)]
                    = s[mt][rh];
    }
    __syncthreads();
    if (tid < 64)
        g_e[m0 + tid] = (red[tid] + red[64 + tid])
                      + (red[128 + tid] + red[192 + tid]);
}

// ---------------------------------------------------------------------------
// Kernel 2: per-batch  w_t = exp(e_t - max), inclusive prefix P_s, ip = 1/P_s.
// ---------------------------------------------------------------------------
__global__ __launch_bounds__(256) void scan_kernel()
{
    __shared__ float se[SS];
    __shared__ float swarp[8];
    __shared__ float sM;
    const int b    = blockIdx.x;
    const int tid  = threadIdx.x;
    const int lane = tid & 31;
    const int wid  = tid >> 5;
    const int base = b * SS;

    GDC_WAIT();
    GDC_LAUNCH();

    for (int i = tid; i < SS; i += 256) se[i] = g_e[base + i];
    __syncthreads();

    float m = -1e30f;
    for (int i = tid; i < SS; i += 256) m = fmaxf(m, se[i]);
#pragma unroll
    for (int o = 16; o; o >>= 1)
        m = fmaxf(m, __shfl_xor_sync(0xffffffffu, m, o));
    if (lane == 0) swarp[wid] = m;
    __syncthreads();
    if (tid == 0) {
        float mm = swarp[0];
#pragma unroll
        for (int i = 1; i < 8; i++) mm = fmaxf(mm, swarp[i]);
        sM = mm;
    }
    __syncthreads();
    const float M = sM;

    const int j0 = tid * 8;
    float wloc[8];
    float run = 0.f;
#pragma unroll
    for (int j = 0; j < 8; j++) {
        wloc[j] = expf(se[j0 + j] - M);
        run += wloc[j];
    }
    float sc = run;
#pragma unroll
    for (int o = 1; o < 32; o <<= 1) {
        const float v = __shfl_up_sync(0xffffffffu, sc, o);
        if (lane >= o) sc += v;
    }
    if (lane == 31) swarp[wid] = sc;
    __syncthreads();
    float woff = 0.f;
    if (wid > 0) {
#pragma unroll
        for (int i = 0; i < 7; i++) if (i < wid) woff += swarp[i];
    }
    float acc = woff + sc - run;
#pragma unroll
    for (int j = 0; j < 8; j++) {
        acc += wloc[j];
        g_w [base + j0 + j] = wloc[j];
        g_ip[base + j0 + j] = 1.0f / acc;
    }
}

// ---------------------------------------------------------------------------
// Kernel 3a: chunk sums T[b,c,h] = sum_{t in chunk} w_t * x[b,t,h]
// ---------------------------------------------------------------------------
__global__ __launch_bounds__(128) void chunk_kernel(const float* __restrict__ x)
{
    __shared__ float sw[CS];
    const int c = blockIdx.x;
    const int b = blockIdx.y;
    const int tbase = b * SS + c * CS;

    GDC_WAIT();
    GDC_LAUNCH();

    if (threadIdx.x < CS) sw[threadIdx.x] = g_w[tbase + threadIdx.x];
    __syncthreads();

    const float4* xp = (const float4*)(x + (size_t)tbase * HH) + threadIdx.x;
    float4 s = make_float4(0.f, 0.f, 0.f, 0.f);
#pragma unroll
    for (int t = 0; t < CS; t++) {
        const float4 v = xp[t * (HH/4)];
        const float w = sw[t];
        s.x = fmaf(w, v.x, s.x);
        s.y = fmaf(w, v.y, s.y);
        s.z = fmaf(w, v.z, s.z);
        s.w = fmaf(w, v.w, s.w);
    }
    __stcg(((float4*)(g_chunk + (size_t)(b * NC + c) * HH)) + threadIdx.x, s);
}

// ---------------------------------------------------------------------------
// Kernel 3p: exclusive prefix over chunks
// ---------------------------------------------------------------------------
__global__ __launch_bounds__(128) void chunkpre_kernel()
{
    GDC_WAIT();
    GDC_LAUNCH();
    const int b = blockIdx.x;
    const int h = blockIdx.y * 128 + threadIdx.x;
    float acc = 0.f;
#pragma unroll 4
    for (int c = 0; c < NC; c++) {
        const size_t idx = (size_t)(b * NC + c) * HH + h;
        const float v = __ldcs(&g_chunk[idx]);
        __stcg(&g_chunkpre[idx], acc);
        acc += v;
    }
}

// ---------------------------------------------------------------------------
// Kernel 3b: a[b,s,h] = (chunkpre + running sum) * ip[b,s]
// ---------------------------------------------------------------------------
__global__ __launch_bounds__(128) void a_kernel(
    const float* __restrict__ x, float* __restrict__ a_out)
{
    __shared__ float sw[CS];
    __shared__ float sip[CS];
    const int c = blockIdx.x;
    const int b = blockIdx.y;
    const int tbase = b * SS + c * CS;

    GDC_WAIT();
    GDC_LAUNCH();

    if (threadIdx.x < CS) {
        sw [threadIdx.x] = g_w [tbase + threadIdx.x];
        sip[threadIdx.x] = g_ip[tbase + threadIdx.x];
    }
    __syncthreads();

    float4 acc = __ldcs(((const float4*)(g_chunkpre + (size_t)(b * NC + c) * HH))
                        + threadIdx.x);

    const float4* xp = (const float4*)(x + (size_t)tbase * HH) + threadIdx.x;
    float4* op = (float4*)(a_out + (size_t)tbase * HH) + threadIdx.x;
#pragma unroll
    for (int t = 0; t < CS; t++) {
        const float4 v = __ldcs(xp + t * (HH/4));
        const float w = sw[t];
        acc.x = fmaf(w, v.x, acc.x);
        acc.y = fmaf(w, v.y, acc.y);
        acc.z = fmaf(w, v.z, acc.z);
        acc.w = fmaf(w, v.w, acc.w);
        const float ip = sip[t];
        __stcs(op + t * (HH/4),
               make_float4(acc.x * ip, acc.y * ip, acc.z * ip, acc.w * ip));
    }
}

// ---------------------------------------------------------------------------
// Kernel 4: d[b,s,t] = (t<=s) ? w[b,t]*ip[b,s] : 0  — 32 rows per CTA,
// 512 threads: one float4 store per thread per row.
// Depends only on scan outputs (3 kernels back) — wait is a formality.
// ---------------------------------------------------------------------------
#define DROWS 32
__global__ __launch_bounds__(512) void d_kernel(float* __restrict__ dd)
{
    __shared__ float4 sw4[SS/4];   // 8 KB
    __shared__ float sip[DROWS];
    const int blk = blockIdx.x;            // 1024 blocks
    const int b  = blk >> 6;               // 64 blocks per batch
    const int s0 = (blk & 63) * DROWS;

    // g_w/g_ip were written by scan_kernel, which completed before our
    // primary (a_kernel) even started — safe to read pre-wait.
    const float4* w4 = (const float4*)(g_w + ((size_t)b << 11));
    if (threadIdx.x < SS/4) sw4[threadIdx.x] = w4[threadIdx.x];
    if (threadIdx.x < DROWS) sip[threadIdx.x] = g_ip[(b << 11) + s0 + threadIdx.x];
    __syncthreads();

    GDC_WAIT();

    const int i  = threadIdx.x;            // float4 index within row
    const int t0 = i * 4;
    const float4 wv = sw4[i];
#pragma unroll 4
    for (int r = 0; r < DROWS; r++) {
        const int s = s0 + r;
        const float ip = sip[r];
        float4 out;
        if (t0 + 3 <= s) {
            out.x = wv.x * ip; out.y = wv.y * ip;
            out.z = wv.z * ip; out.w = wv.w * ip;
        } else if (t0 > s) {
            out.x = out.y = out.z = out.w = 0.f;
        } else {
            out.x = (t0     <= s) ? wv.x * ip : 0.f;
            out.y = (t0 + 1 <= s) ? wv.y * ip : 0.f;
            out.z = (t0 + 2 <= s) ? wv.z * ip : 0.f;
            out.w = (t0 + 3 <= s) ? wv.w * ip : 0.f;
        }
        __stcs((float4*)(dd + ((size_t)(b << 11) + s) * SS) + i, out);
    }
}

// ---------------------------------------------------------------------------
static void launch_pdl(const void* func, dim3 grid, dim3 block, size_t smem,
                       void** args)
{
    cudaLaunchConfig_t cfg = {};
    cfg.gridDim = grid;
    cfg.blockDim = block;
    cfg.dynamicSmemBytes = smem;
    cfg.stream = 0;
    cudaLaunchAttribute attr[1];
    attr[0].id = cudaLaunchAttributeProgrammaticStreamSerialization;
    attr[0].val.programmaticStreamSerializationAllowed = 1;
    cfg.attrs = attr;
    cfg.numAttrs = 1;
    cudaLaunchKernelExC(&cfg, func, args);
}

extern "C" void kernel_launch(void* const* d_in, const int* in_sizes, int n_in,
                              void* d_out, int out_size)
{
    const float* x = (const float*)d_in[0];   // [B,S,H]
    const float* W = (const float*)d_in[1];   // [A,H]
    const float* q = (const float*)d_in[2];   // [1,A]
    float* a_out = (float*)d_out;             // [B,S,1,H]
    float* dd    = (float*)d_out + A_ELEMS;   // [B,S,1,S]

    cudaFuncSetAttribute(e_mma_kernel,
                         cudaFuncAttributeMaxDynamicSharedMemorySize, SM_TOTAL);

    wsplit_kernel<<<AA * HH / 512, 256>>>(W);

    {   // e_mma (PDL secondary of wsplit)
        void* args[] = { (void*)&x, (void*)&q };
        launch_pdl((const void*)e_mma_kernel, dim3(BS / 64), dim3(256),
                   SM_TOTAL, args);
    }
    {   // scan
        void* args[] = { nullptr };
        launch_pdl((const void*)scan_kernel, dim3(BB), dim3(256), 0, args);
    }
    {   // chunk
        void* args[] = { (void*)&x };
        launch_pdl((const void*)chunk_kernel, dim3(NC, BB), dim3(128), 0, args);
    }
    {   // chunkpre
        void* args[] = { nullptr };
        launch_pdl((const void*)chunkpre_kernel, dim3(BB, HH / 128), dim3(128),
                   0, args);
    }
    {   // a
        void* args[] = { (void*)&x, (void*)&a_out };
        launch_pdl((const void*)a_kernel, dim3(NC, BB), dim3(128), 0, args);
    }
    {   // d
        void* args[] = { (void*)&dd };
        launch_pdl((const void*)d_kernel, dim3(BS / DROWS), dim3(512), 0, args);
    }
}

// round 17
// speedup vs baseline: 1.2079x; 1.0011x over previous
#include <cuda_runtime.h>
#include <cuda_fp16.h>
#include <cstdint>

// Problem constants
#define BB 16
#define SS 2048
#define HH 512
#define AA 256
#define BS (BB*SS)               // 32768 tokens
#define A_ELEMS ((size_t)BS*HH)  // offset of d in output

// Scratch (device globals — no allocation allowed)
__device__ float g_e[BS];
__device__ float g_w[BS];
__device__ float g_ip[BS];
#define NC 128
#define CS 16
__device__ float g_chunk[BB*NC*HH];     // 4 MB
__device__ float g_chunkpre[BB*NC*HH];  // 4 MB (exclusive prefix)
// W as fp16 pairs (uint32 = half2), [256 rows][256 pairs]
__device__ unsigned int g_wh[AA*HH/2];
// fp16 copy of x, written by e_mma (free: it already converts), read by chunk/a
__device__ __half g_xh[A_ELEMS];        // 32 MB

// ---------------------------------------------------------------------------
#define GDC_WAIT()   asm volatile("griddepcontrol.wait;" ::: "memory")
#define GDC_LAUNCH() asm volatile("griddepcontrol.launch_dependents;" ::: "memory")

__device__ __forceinline__ uint32_t smem_u32(const void* p) {
    uint32_t a;
    asm("{ .reg .u64 t; cvta.to.shared.u64 t, %1; cvt.u32.u64 %0, t; }"
        : "=r"(a) : "l"(p));
    return a;
}

#define LDSM_X4(r, addr) \
    asm volatile("ldmatrix.sync.aligned.m8n8.x4.shared.b16 {%0,%1,%2,%3}, [%4];" \
        : "=r"((r)[0]), "=r"((r)[1]), "=r"((r)[2]), "=r"((r)[3]) : "r"(addr))

#define HMMA16816(d, a, b0, b1) \
    asm volatile("mma.sync.aligned.m16n8k16.row.col.f32.f16.f16.f32 " \
        "{%0,%1,%2,%3},{%4,%5,%6,%7},{%8,%9},{%0,%1,%2,%3};" \
        : "+f"((d)[0]), "+f"((d)[1]), "+f"((d)[2]), "+f"((d)[3]) \
        : "r"((a)[0]), "r"((a)[1]), "r"((a)[2]), "r"((a)[3]), "r"(b0), "r"(b1))

#define CP_ASYNC16(dst, src) \
    asm volatile("cp.async.cg.shared.global [%0], [%1], 16;" \
                 :: "r"(dst), "l"(src) : "memory")
#define CP_COMMIT()  asm volatile("cp.async.commit_group;" ::: "memory")
#define CP_WAIT0()   asm volatile("cp.async.wait_group 0;" ::: "memory")

__device__ __forceinline__ float fast_tanh(float v) {
    float t; asm("ex2.approx.f32 %0, %1;" : "=f"(t) : "f"(v * 2.885390081777927f));
    float r; asm("rcp.approx.f32 %0, %1;" : "=f"(r) : "f"(t + 1.0f));
    return fmaf(-2.0f, r, 1.0f);   // tanh(v) = 1 - 2/(e^{2v}+1)
}

// ---------------------------------------------------------------------------
// Kernel 0: W [256,512] fp32 -> fp16 pairs
// ---------------------------------------------------------------------------
__global__ __launch_bounds__(256) void wsplit_kernel(const float* __restrict__ W)
{
    GDC_LAUNCH();
    const int i = blockIdx.x * 256 + threadIdx.x;   // pair index
    const float2 v = ((const float2*)W)[i];
    __half2 hp = __floats2half2_rn(v.x, v.y);
    g_wh[i] = *(unsigned int*)&hp;
}

// ---------------------------------------------------------------------------
// Kernel 1: e[t] = sum_a q[a]*tanh( (W x)[t,a] ) via mma.sync fp16.
// CTA tile: M=64 tokens x N=256 (FULL A). 8 warps as 2(m) x 4(n).
// Double-buffered; W via cp.async, X via regs (fp32->fp16 convert).
// Side effect: writes the fp16 copy of x (g_xh) for the chunk/a kernels.
// ---------------------------------------------------------------------------
#define RSTRIDE 144              // bytes per smem row (64 fp16 + pad)
#define BUFSZ   46080            // X(64*144=9216) + W(256*144=36864)
#define SM_W_OFF 9216
#define SM_Q    92160            // 256 floats
#define SM_TOTAL 93184

__global__ __launch_bounds__(256, 2) void e_mma_kernel(
    const float* __restrict__ x, const float* __restrict__ q)
{
    extern __shared__ __align__(128) char smem[];
    const uint32_t sb = smem_u32(smem);
    const int tid  = threadIdx.x;
    const int lane = tid & 31;
    const int warp = tid >> 5;
    const int warp_m = warp & 1;
    const int warp_n = warp >> 1;
    const size_t m0 = (size_t)blockIdx.x * 64;

    float* sq = (float*)(smem + SM_Q);
    sq[tid] = q[tid];

    float acc[2][8][4];
#pragma unroll
    for (int mt = 0; mt < 2; mt++)
#pragma unroll
        for (int nt = 0; nt < 8; nt++)
#pragma unroll
            for (int j = 0; j < 4; j++) acc[mt][nt][j] = 0.f;

    const uint32_t a_off = (lane & 15) * RSTRIDE + ((lane >> 4) << 4);
    const uint32_t b_off = ((((lane >> 4) & 1) << 3) + (lane & 7)) * RSTRIDE
                         + (((lane >> 3) & 1) << 4);
    const uint32_t ax0 = sb + warp_m * 32 * RSTRIDE + a_off;
    const uint32_t bw0 = sb + SM_W_OFF + warp_n * 64 * RSTRIDE + b_off;

    const uint4* wh4 = (const uint4*)g_wh;   // [a][64 uint4 per row]

    // Prologue: fill buffer 0 for chunk 0
    {
        float4 xv[4];
#pragma unroll
        for (int i = 0; i < 4; i++) {
            const int idx = i * 256 + tid;
            xv[i] = *(const float4*)(x + (m0 + (idx >> 4)) * HH + (idx & 15) * 4);
        }
        GDC_WAIT();            // g_wh ready (wsplit done)
        GDC_LAUNCH();          // let scan roll out during our execution
#pragma unroll
        for (int i = 0; i < 8; i++) {
            const int g  = i * 256 + tid;
            const int row = g >> 3;
            const int cc  = g & 7;
            CP_ASYNC16(sb + SM_W_OFF + row * RSTRIDE + cc * 16,
                       wh4 + (size_t)row * 64 + cc);
        }
        CP_COMMIT();
#pragma unroll
        for (int i = 0; i < 4; i++) {
            const int idx = i * 256 + tid;
            const uint32_t bo = (idx >> 4) * RSTRIDE + (idx & 15) * 8;
            __half2 h01 = __floats2half2_rn(xv[i].x, xv[i].y);
            __half2 h23 = __floats2half2_rn(xv[i].z, xv[i].w);
            unsigned long long hp;
            asm("mov.b64 %0, {%1, %2};" : "=l"(hp)
                : "r"(*(unsigned int*)&h01), "r"(*(unsigned int*)&h23));
            *(unsigned long long*)(smem + bo) = hp;
            *(unsigned long long*)(&g_xh[(m0 + (idx >> 4)) * HH + (idx & 15) * 4]) = hp;
        }
        CP_WAIT0();
        __syncthreads();
    }

    for (int c = 0; c < 8; c++) {
        const uint32_t cur = (c & 1) * BUFSZ;
        const uint32_t nxt = ((c + 1) & 1) * BUFSZ;

        float4 xv[4];
        if (c < 7) {
            const int kk = (c + 1) * 64;
#pragma unroll
            for (int i = 0; i < 4; i++) {
                const int idx = i * 256 + tid;
                xv[i] = *(const float4*)(x + (m0 + (idx >> 4)) * HH + kk + (idx & 15) * 4);
            }
#pragma unroll
            for (int i = 0; i < 8; i++) {
                const int g  = i * 256 + tid;
                const int row = g >> 3;
                const int cc  = g & 7;
                CP_ASYNC16(sb + nxt + SM_W_OFF + row * RSTRIDE + cc * 16,
                           wh4 + (size_t)row * 64 + (kk >> 3) + cc);
            }
            CP_COMMIT();
        }

        const uint32_t ax = ax0 + cur;
        const uint32_t bw = bw0 + cur;
#pragma unroll
        for (int ks = 0; ks < 4; ks++) {
            uint32_t Bv[16];
#pragma unroll
            for (int jp = 0; jp < 4; jp++)
                LDSM_X4(&Bv[jp * 4], bw + jp * 16 * RSTRIDE + ks * 32);
            uint32_t A0[4], A1[4];
            LDSM_X4(A0, ax + ks * 32);
            LDSM_X4(A1, ax + 16 * RSTRIDE + ks * 32);
#pragma unroll
            for (int nt = 0; nt < 8; nt++) {
                const int bi = (nt >> 1) * 4 + (nt & 1) * 2;
                HMMA16816(acc[0][nt], A0, Bv[bi], Bv[bi + 1]);
            }
#pragma unroll
            for (int nt = 0; nt < 8; nt++) {
                const int bi = (nt >> 1) * 4 + (nt & 1) * 2;
                HMMA16816(acc[1][nt], A1, Bv[bi], Bv[bi + 1]);
            }
        }

        if (c < 7) {
            const int kk = (c + 1) * 64;
#pragma unroll
            for (int i = 0; i < 4; i++) {
                const int idx = i * 256 + tid;
                const uint32_t bo = (idx >> 4) * RSTRIDE + (idx & 15) * 8;
                __half2 h01 = __floats2half2_rn(xv[i].x, xv[i].y);
                __half2 h23 = __floats2half2_rn(xv[i].z, xv[i].w);
                unsigned long long hp;
                asm("mov.b64 %0, {%1, %2};" : "=l"(hp)
                    : "r"(*(unsigned int*)&h01), "r"(*(unsigned int*)&h23));
                *(unsigned long long*)(smem + nxt + bo) = hp;
                *(unsigned long long*)(&g_xh[(m0 + (idx >> 4)) * HH + kk + (idx & 15) * 4]) = hp;
            }
            CP_WAIT0();
            __syncthreads();
        }
    }

    // Epilogue: s = sum_cols q[col]*tanh(D) per owned row
    float s[2][2] = {{0.f, 0.f}, {0.f, 0.f}};
#pragma unroll
    for (int mt = 0; mt < 2; mt++)
#pragma unroll
        for (int nt = 0; nt < 8; nt++) {
            const int col = warp_n * 64 + nt * 8 + 2 * (lane & 3);
            const float q0 = sq[col], q1 = sq[col + 1];
            s[mt][0] = fmaf(q0, fast_tanh(acc[mt][nt][0]),
                       fmaf(q1, fast_tanh(acc[mt][nt][1]), s[mt][0]));
            s[mt][1] = fmaf(q0, fast_tanh(acc[mt][nt][2]),
                       fmaf(q1, fast_tanh(acc[mt][nt][3]), s[mt][1]));
        }
#pragma unroll
    for (int mt = 0; mt < 2; mt++)
#pragma unroll
        for (int rh = 0; rh < 2; rh++) {
            float v = s[mt][rh];
            v += __shfl_xor_sync(0xffffffffu, v, 1);
            v += __shfl_xor_sync(0xffffffffu, v, 2);
            s[mt][rh] = v;
        }

    __syncthreads();               // all ldmatrix done; reuse smem
    float* red = (float*)smem;     // [4 warp_n][64 rows]
    if ((lane & 3) == 0) {
#pragma unroll
        for (int mt = 0; mt < 2; mt++)
#pragma unroll
            for (int rh = 0; rh < 2; rh++)
                red[warp_n * 64 + warp_m * 32 + mt * 16 + rh * 8 + (lane >> 2)]
                    = s[mt][rh];
    }
    __syncthreads();
    if (tid < 64)
        g_e[m0 + tid] = (red[tid] + red[64 + tid])
                      + (red[128 + tid] + red[192 + tid]);
}

// ---------------------------------------------------------------------------
// Kernel 2: per-batch  w_t = exp(e_t - max), inclusive prefix P_s, ip = 1/P_s.
// ---------------------------------------------------------------------------
__global__ __launch_bounds__(256) void scan_kernel()
{
    __shared__ float se[SS];
    __shared__ float swarp[8];
    __shared__ float sM;
    const int b    = blockIdx.x;
    const int tid  = threadIdx.x;
    const int lane = tid & 31;
    const int wid  = tid >> 5;
    const int base = b * SS;

    GDC_WAIT();
    GDC_LAUNCH();

    for (int i = tid; i < SS; i += 256) se[i] = g_e[base + i];
    __syncthreads();

    float m = -1e30f;
    for (int i = tid; i < SS; i += 256) m = fmaxf(m, se[i]);
#pragma unroll
    for (int o = 16; o; o >>= 1)
        m = fmaxf(m, __shfl_xor_sync(0xffffffffu, m, o));
    if (lane == 0) swarp[wid] = m;
    __syncthreads();
    if (tid == 0) {
        float mm = swarp[0];
#pragma unroll
        for (int i = 1; i < 8; i++) mm = fmaxf(mm, swarp[i]);
        sM = mm;
    }
    __syncthreads();
    const float M = sM;

    const int j0 = tid * 8;
    float wloc[8];
    float run = 0.f;
#pragma unroll
    for (int j = 0; j < 8; j++) {
        wloc[j] = expf(se[j0 + j] - M);
        run += wloc[j];
    }
    float sc = run;
#pragma unroll
    for (int o = 1; o < 32; o <<= 1) {
        const float v = __shfl_up_sync(0xffffffffu, sc, o);
        if (lane >= o) sc += v;
    }
    if (lane == 31) swarp[wid] = sc;
    __syncthreads();
    float woff = 0.f;
    if (wid > 0) {
#pragma unroll
        for (int i = 0; i < 7; i++) if (i < wid) woff += swarp[i];
    }
    float acc = woff + sc - run;
#pragma unroll
    for (int j = 0; j < 8; j++) {
        acc += wloc[j];
        g_w [base + j0 + j] = wloc[j];
        g_ip[base + j0 + j] = 1.0f / acc;
    }
}

// ---------------------------------------------------------------------------
// Kernel 3a: chunk sums T[b,c,h] = sum_{t in chunk} w_t * xh[b,t,h]
// x read as fp16 (g_xh) — half the bytes. fp32 accumulation.
// ---------------------------------------------------------------------------
__global__ __launch_bounds__(128) void chunk_kernel()
{
    __shared__ float sw[CS];
    const int c = blockIdx.x;
    const int b = blockIdx.y;
    const int tbase = b * SS + c * CS;

    GDC_WAIT();
    GDC_LAUNCH();

    if (threadIdx.x < CS) sw[threadIdx.x] = g_w[tbase + threadIdx.x];
    __syncthreads();

    const uint2* xp = (const uint2*)(g_xh + (size_t)tbase * HH) + threadIdx.x;
    float4 s = make_float4(0.f, 0.f, 0.f, 0.f);
#pragma unroll
    for (int t = 0; t < CS; t++) {
        const uint2 raw = xp[t * (HH/4)];
        const float2 f01 = __half22float2(*(const __half2*)&raw.x);
        const float2 f23 = __half22float2(*(const __half2*)&raw.y);
        const float w = sw[t];
        s.x = fmaf(w, f01.x, s.x);
        s.y = fmaf(w, f01.y, s.y);
        s.z = fmaf(w, f23.x, s.z);
        s.w = fmaf(w, f23.y, s.w);
    }
    __stcg(((float4*)(g_chunk + (size_t)(b * NC + c) * HH)) + threadIdx.x, s);
}

// ---------------------------------------------------------------------------
// Kernel 3p: exclusive prefix over chunks
// ---------------------------------------------------------------------------
__global__ __launch_bounds__(128) void chunkpre_kernel()
{
    GDC_WAIT();
    GDC_LAUNCH();
    const int b = blockIdx.x;
    const int h = blockIdx.y * 128 + threadIdx.x;
    float acc = 0.f;
#pragma unroll 4
    for (int c = 0; c < NC; c++) {
        const size_t idx = (size_t)(b * NC + c) * HH + h;
        const float v = __ldcs(&g_chunk[idx]);
        __stcg(&g_chunkpre[idx], acc);
        acc += v;
    }
}

// ---------------------------------------------------------------------------
// Kernel 3b: a[b,s,h] = (chunkpre + running sum) * ip[b,s]
// x read as fp16 (g_xh); fp32 accumulation; fp32 output.
// ---------------------------------------------------------------------------
__global__ __launch_bounds__(128) void a_kernel(float* __restrict__ a_out)
{
    __shared__ float sw[CS];
    __shared__ float sip[CS];
    const int c = blockIdx.x;
    const int b = blockIdx.y;
    const int tbase = b * SS + c * CS;

    GDC_WAIT();
    GDC_LAUNCH();

    if (threadIdx.x < CS) {
        sw [threadIdx.x] = g_w [tbase + threadIdx.x];
        sip[threadIdx.x] = g_ip[tbase + threadIdx.x];
    }
    __syncthreads();

    float4 acc = __ldcs(((const float4*)(g_chunkpre + (size_t)(b * NC + c) * HH))
                        + threadIdx.x);

    const uint2* xp = (const uint2*)(g_xh + (size_t)tbase * HH) + threadIdx.x;
    float4* op = (float4*)(a_out + (size_t)tbase * HH) + threadIdx.x;
#pragma unroll
    for (int t = 0; t < CS; t++) {
        const uint2 raw = __ldcs(xp + t * (HH/4));
        const float2 f01 = __half22float2(*(const __half2*)&raw.x);
        const float2 f23 = __half22float2(*(const __half2*)&raw.y);
        const float w = sw[t];
        acc.x = fmaf(w, f01.x, acc.x);
        acc.y = fmaf(w, f01.y, acc.y);
        acc.z = fmaf(w, f23.x, acc.z);
        acc.w = fmaf(w, f23.y, acc.w);
        const float ip = sip[t];
        __stcs(op + t * (HH/4),
               make_float4(acc.x * ip, acc.y * ip, acc.z * ip, acc.w * ip));
    }
}

// ---------------------------------------------------------------------------
// Kernel 4: d[b,s,t] = (t<=s) ? w[b,t]*ip[b,s] : 0  — 32 rows per CTA,
// 512 threads, per-thread direct w load (no smem staging needed).
// ---------------------------------------------------------------------------
#define DROWS 32
__global__ __launch_bounds__(512) void d_kernel(float* __restrict__ dd)
{
    __shared__ float sip[DROWS];
    const int blk = blockIdx.x;            // 1024 blocks
    const int b  = blk >> 6;               // 64 blocks per batch
    const int s0 = (blk & 63) * DROWS;

    // g_w/g_ip written by scan_kernel (completed long before our primary).
    const float4 wv = ((const float4*)(g_w + ((size_t)b << 11)))[threadIdx.x];
    if (threadIdx.x < DROWS) sip[threadIdx.x] = g_ip[(b << 11) + s0 + threadIdx.x];
    __syncthreads();

    GDC_WAIT();

    const int i  = threadIdx.x;            // float4 index within row
    const int t0 = i * 4;
#pragma unroll 4
    for (int r = 0; r < DROWS; r++) {
        const int s = s0 + r;
        const float ip = sip[r];
        float4 out;
        if (t0 + 3 <= s) {
            out.x = wv.x * ip; out.y = wv.y * ip;
            out.z = wv.z * ip; out.w = wv.w * ip;
        } else if (t0 > s) {
            out.x = out.y = out.z = out.w = 0.f;
        } else {
            out.x = (t0     <= s) ? wv.x * ip : 0.f;
            out.y = (t0 + 1 <= s) ? wv.y * ip : 0.f;
            out.z = (t0 + 2 <= s) ? wv.z * ip : 0.f;
            out.w = (t0 + 3 <= s) ? wv.w * ip : 0.f;
        }
        __stcs((float4*)(dd + ((size_t)(b << 11) + s) * SS) + i, out);
    }
}

// ---------------------------------------------------------------------------
static void launch_pdl(const void* func, dim3 grid, dim3 block, size_t smem,
                       void** args)
{
    cudaLaunchConfig_t cfg = {};
    cfg.gridDim = grid;
    cfg.blockDim = block;
    cfg.dynamicSmemBytes = smem;
    cfg.stream = 0;
    cudaLaunchAttribute attr[1];
    attr[0].id = cudaLaunchAttributeProgrammaticStreamSerialization;
    attr[0].val.programmaticStreamSerializationAllowed = 1;
    cfg.attrs = attr;
    cfg.numAttrs = 1;
    cudaLaunchKernelExC(&cfg, func, args);
}

extern "C" void kernel_launch(void* const* d_in, const int* in_sizes, int n_in,
                              void* d_out, int out_size)
{
    const float* x = (const float*)d_in[0];   // [B,S,H]
    const float* W = (const float*)d_in[1];   // [A,H]
    const float* q = (const float*)d_in[2];   // [1,A]
    float* a_out = (float*)d_out;             // [B,S,1,H]
    float* dd    = (float*)d_out + A_ELEMS;   // [B,S,1,S]

    cudaFuncSetAttribute(e_mma_kernel,
                         cudaFuncAttributeMaxDynamicSharedMemorySize, SM_TOTAL);

    wsplit_kernel<<<AA * HH / 512, 256>>>(W);

    {   // e_mma (PDL secondary of wsplit)
        void* args[] = { (void*)&x, (void*)&q };
        launch_pdl((const void*)e_mma_kernel, dim3(BS / 64), dim3(256),
                   SM_TOTAL, args);
    }
    {   // scan
        void* args[] = { nullptr };
        launch_pdl((const void*)scan_kernel, dim3(BB), dim3(256), 0, args);
    }
    {   // chunk
        void* args[] = { nullptr };
        launch_pdl((const void*)chunk_kernel, dim3(NC, BB), dim3(128), 0, args);
    }
    {   // chunkpre
        void* args[] = { nullptr };
        launch_pdl((const void*)chunkpre_kernel, dim3(BB, HH / 128), dim3(128),
                   0, args);
    }
    {   // a
        void* args[] = { (void*)&a_out };
        launch_pdl((const void*)a_kernel, dim3(NC, BB), dim3(128), 0, args);
    }
    {   // d
        void* args[] = { (void*)&dd };
        launch_pdl((const void*)d_kernel, dim3(BS / DROWS), dim3(512), 0, args);
    }
}